// round 4
// baseline (speedup 1.0000x reference)
#include <cuda_runtime.h>
#include <cuda_fp16.h>

// Problem constants
#define D_IN   4096
#define D_HID  2048
#define D_OUT  512
#define NBATCH 8192
#define NNZ1   32768
#define NNZ2   8192
#define TB     32     // batch rows per block; lane = batch
#define NPH    4      // x column phases (1024 cols each)
#define PHC    1024
#define SUB1   24     // edge slots per (row, phase): Poisson(4), overflow ~1e-13
#define SUB2   64     // edge slots per layer-2 row: Poisson(16)
#define XS_STRIDE 1025   // floats per batch row in smem (pad -> conflict-free)
#define HS_STRIDE 2050   // halves per batch row in smem (pad -> conflict-free)

// ---------------- scratch (__device__ globals) -------------------------------
__device__ float2 g_e1[D_HID * NPH * SUB1];           // {w, byteoff} 1.5 MB
__device__ float2 g_e2[D_OUT * SUB2];                 // 256 KB
__device__ int    g_c1[D_HID * NPH];
__device__ int    g_c2[D_OUT];
__device__ __half g_h[(size_t)NBATCH * D_HID];        // 32 MB intermediate h

// ---------------- prep -------------------------------------------------------
__global__ void k_zero() {
    int i = blockIdx.x * blockDim.x + threadIdx.x;
    if (i < D_HID * NPH) g_c1[i] = 0;
    if (i < D_OUT)       g_c2[i] = 0;
}

__global__ void k_scatter(const float* __restrict__ w1, const int* __restrict__ rows1,
                          const int* __restrict__ cols1,
                          const float* __restrict__ w2, const int* __restrict__ rows2,
                          const int* __restrict__ cols2) {
    int e = blockIdx.x * blockDim.x + threadIdx.x;
    if (e < NNZ1) {
        int r = rows1[e], c = cols1[e];
        int cell = r * NPH + (c >> 10);
        int p = atomicAdd(&g_c1[cell], 1);
        if (p < SUB1)   // byte offset of local col within the phase tile row
            g_e1[cell * SUB1 + p] = make_float2(w1[e], __int_as_float((c & 1023) * 4));
    }
    if (e < NNZ2) {
        int r = rows2[e], c = cols2[e];
        int p = atomicAdd(&g_c2[r], 1);
        if (p < SUB2)   // byte offset of fp16 h element within batch row
            g_e2[r * SUB2 + p] = make_float2(w2[e], __int_as_float(c * 2));
    }
}

// ---------------- layer 1: h = sigmoid(W1 x + b1) ----------------------------
// Block = 32 batches (lane = batch). Warp owns 32 rows per half (2 halves).
// x staged per column-phase: xs[batch][localcol], stride 1025 floats ->
// gather addr = xs + lane*4100 + byteoff : banks (lane + col) % 32, 1 wavefront.
__global__ __launch_bounds__(1024, 1)
void k_l1(const float* __restrict__ x, const float* __restrict__ b1) {
    extern __shared__ char smem[];
    float*  xs  = reinterpret_cast<float*>(smem);                    // 32*1025*4 = 131200 B
    __half* hst = reinterpret_cast<__half*>(smem + 32 * XS_STRIDE * 4); // 32 warps * 32*34*2

    const int tid  = threadIdx.x;
    const int w    = tid >> 5;
    const int lane = tid & 31;
    const int b0   = blockIdx.x * TB;
    const char*  xs_lane = reinterpret_cast<const char*>(xs) + lane * (XS_STRIDE * 4);
    __half*      hmy     = hst + w * (32 * 34);

    #pragma unroll 1
    for (int hp = 0; hp < 2; hp++) {
        const int row0 = hp * 1024 + w * 32;
        float acc[32];
        #pragma unroll
        for (int j = 0; j < 32; j++) acc[j] = __ldg(b1 + row0 + j);

        #pragma unroll 1
        for (int xp = 0; xp < NPH; xp++) {
            __syncthreads();   // previous phase gathers done before overwrite
            {   // stage: warp w loads batch b0+w, conflict-free scalar STS
                const float* xr = x + (size_t)(b0 + w) * D_IN + xp * PHC;
                float*       xw = xs + w * XS_STRIDE;
                #pragma unroll
                for (int it = 0; it < PHC / 32; it++)
                    xw[it * 32 + lane] = __ldg(xr + it * 32 + lane);
            }
            __syncthreads();

            #pragma unroll
            for (int j = 0; j < 32; j++) {
                const int cell = (row0 + j) * NPH + xp;
                int n = g_c1[cell];
                n = min(n, SUB1);
                const float4* ep = reinterpret_cast<const float4*>(g_e1 + cell * SUB1);
                float a = acc[j];
                const int npair = n >> 1;
                for (int i = 0; i < npair; i++) {
                    float4 E = ep[i];
                    a += E.x * *reinterpret_cast<const float*>(xs_lane + __float_as_int(E.y));
                    a += E.z * *reinterpret_cast<const float*>(xs_lane + __float_as_int(E.w));
                }
                if (n & 1) {
                    float2 E = reinterpret_cast<const float2*>(ep)[n - 1];
                    a += E.x * *reinterpret_cast<const float*>(xs_lane + __float_as_int(E.y));
                }
                acc[j] = a;
            }
        }

        // sigmoid -> per-warp transpose stage -> coalesced fp16 STG
        #pragma unroll
        for (int j = 0; j < 32; j++) {
            float s = __fdividef(1.0f, 1.0f + __expf(-acc[j]));
            hmy[lane * 34 + j] = __float2half(s);    // hst[batch][rowlocal]
        }
        __syncwarp();
        #pragma unroll 1
        for (int b = 0; b < 32; b++) {
            if (lane < 16) {   // 16 lanes store 32 halves of batch b's 32 rows
                unsigned v = *reinterpret_cast<const unsigned*>(hmy + b * 34 + lane * 2);
                *reinterpret_cast<unsigned*>(
                    &g_h[(size_t)(b0 + b) * D_HID + row0 + lane * 2]) = v;
            }
        }
        __syncwarp();
    }
}

// ---------------- layer 2: out = W2 h + b2 -----------------------------------
// Whole fp16 h tile in smem: hs[batch][hid], stride 2050 halves.
// gather addr = hs + lane*4100 + c*2 : banks (lane + c/2) % 32, 1 wavefront.
__global__ __launch_bounds__(1024, 1)
void k_l2(const float* __restrict__ b2, float* __restrict__ out) {
    extern __shared__ char smem[];
    __half* hs  = reinterpret_cast<__half*>(smem);                     // 32*2050*2 = 131200 B
    float*  ost = reinterpret_cast<float*>(smem + 32 * HS_STRIDE * 2); // 512*33*4

    const int tid  = threadIdx.x;
    const int w    = tid >> 5;
    const int lane = tid & 31;
    const int b0   = blockIdx.x * TB;
    const char* hs_lane = reinterpret_cast<const char*>(hs) + lane * (HS_STRIDE * 2);

    {   // stage h tile: warp w loads batch b0+w (uints = 2 halves), conflict-free STS
        const unsigned* hr = reinterpret_cast<const unsigned*>(g_h + (size_t)(b0 + w) * D_HID);
        unsigned* hw = reinterpret_cast<unsigned*>(smem + w * (HS_STRIDE * 2));
        #pragma unroll
        for (int it = 0; it < D_HID / 64; it++)
            hw[it * 32 + lane] = __ldg(hr + it * 32 + lane);
    }
    __syncthreads();

    #pragma unroll 1
    for (int j = 0; j < 16; j++) {
        const int r = w * 16 + j;
        int n = g_c2[r];
        n = min(n, SUB2);
        const float4* ep = reinterpret_cast<const float4*>(g_e2 + r * SUB2);
        float a = __ldg(b2 + r);
        const int npair = n >> 1;
        #pragma unroll 2
        for (int i = 0; i < npair; i++) {
            float4 E = ep[i];
            a += E.x * __half2float(*reinterpret_cast<const __half*>(
                           hs_lane + __float_as_int(E.y)));
            a += E.z * __half2float(*reinterpret_cast<const __half*>(
                           hs_lane + __float_as_int(E.w)));
        }
        if (n & 1) {
            float2 E = reinterpret_cast<const float2*>(ep)[n - 1];
            a += E.x * __half2float(*reinterpret_cast<const __half*>(
                           hs_lane + __float_as_int(E.y)));
        }
        ost[r * 33 + lane] = a;    // banks (r + lane) % 32, conflict-free
    }
    __syncthreads();

    #pragma unroll
    for (int it = 0; it < 16; it++) {   // coalesced output copy
        int idx = it * 1024 + tid;
        int b = idx >> 9, r = idx & 511;
        out[(size_t)(b0 + b) * D_OUT + r] = ost[r * 33 + b];
    }
}

// ---------------- launch -----------------------------------------------------
extern "C" void kernel_launch(void* const* d_in, const int* in_sizes, int n_in,
                              void* d_out, int out_size) {
    const float* x     = (const float*)d_in[0];
    const float* w1    = (const float*)d_in[1];
    const float* b1    = (const float*)d_in[2];
    const float* w2    = (const float*)d_in[3];
    const float* b2    = (const float*)d_in[4];
    const int*   rows1 = (const int*)d_in[5];
    const int*   cols1 = (const int*)d_in[6];
    const int*   rows2 = (const int*)d_in[7];
    const int*   cols2 = (const int*)d_in[8];
    float*       out   = (float*)d_out;

    k_zero<<<(D_HID * NPH + 255) / 256, 256>>>();
    k_scatter<<<NNZ1 / 256, 256>>>(w1, rows1, cols1, w2, rows2, cols2);

    const int SMEM1 = 32 * XS_STRIDE * 4 + 32 * (32 * 34) * 2;   // 131200 + 69632
    const int SMEM2 = 32 * HS_STRIDE * 2 + 512 * 33 * 4;         // 131200 + 67584
    cudaFuncSetAttribute(k_l1, cudaFuncAttributeMaxDynamicSharedMemorySize, SMEM1);
    cudaFuncSetAttribute(k_l2, cudaFuncAttributeMaxDynamicSharedMemorySize, SMEM2);
    k_l1<<<NBATCH / TB, 1024, SMEM1>>>(x, b1);
    k_l2<<<NBATCH / TB, 1024, SMEM2>>>(b2, out);
}

// round 6
// speedup vs baseline: 1.6058x; 1.6058x over previous
#include <cuda_runtime.h>
#include <cuda_fp16.h>

// Problem constants
#define D_IN    4096
#define D_HID   2048
#define D_OUT   512
#define NBATCH  8192
#define NNZ1    32768
#define NNZ2    8192
#define NPH     2
#define PHC     2048                 // x cols per phase
#define NCELL1  (NPH * D_HID)        // 4096 (cell = phase*D_HID + row)
#define XS_STRIDE 2050               // halves per batch row (odd word stride -> 1-wf gather)
#define HS_STRIDE 34                 // halves per h row in k_l2 (64B span + pad)

// ---------------- scratch (__device__ globals) -------------------------------
__device__ float2 g_e1[NNZ1];        // CSR edges {w, __int_as_float(byteoff)}
__device__ float2 g_e2[NNZ2];
__device__ int    g_rp1[NCELL1 + 1];
__device__ int    g_rp2[D_OUT + 1];
__device__ int    g_cur1[NCELL1];
__device__ int    g_cur2[D_OUT];
__device__ __half g_h[(size_t)D_HID * NBATCH];   // h[row][batch], 32 MB

// ---------------- prep 1: hist + scan in ONE block ---------------------------
__global__ __launch_bounds__(1024, 1)
void k_prep(const int* __restrict__ rows1, const int* __restrict__ cols1,
            const int* __restrict__ rows2) {
    __shared__ int h1[NCELL1];       // 16 KB
    __shared__ int h2[D_OUT];
    __shared__ int ss[1024];
    const int t = threadIdx.x;

    for (int i = t; i < NCELL1; i += 1024) h1[i] = 0;
    for (int i = t; i < D_OUT;  i += 1024) h2[i] = 0;
    __syncthreads();
    for (int e = t; e < NNZ1; e += 1024) {
        int cell = (__ldg(cols1 + e) >> 11) * D_HID + __ldg(rows1 + e);
        atomicAdd(&h1[cell], 1);
    }
    for (int e = t; e < NNZ2; e += 1024) atomicAdd(&h2[__ldg(rows2 + e)], 1);
    __syncthreads();

    // scan h1 (4096 = 4/thread)
    int l0 = h1[t*4], l1 = h1[t*4+1], l2 = h1[t*4+2], l3 = h1[t*4+3];
    ss[t] = l0 + l1 + l2 + l3;
    __syncthreads();
    for (int off = 1; off < 1024; off <<= 1) {
        int v = (t >= off) ? ss[t - off] : 0;
        __syncthreads();
        ss[t] += v;
        __syncthreads();
    }
    int ex = (t == 0) ? 0 : ss[t - 1];
    g_rp1[t*4] = ex; g_cur1[t*4] = ex; ex += l0;
    g_rp1[t*4+1] = ex; g_cur1[t*4+1] = ex; ex += l1;
    g_rp1[t*4+2] = ex; g_cur1[t*4+2] = ex; ex += l2;
    g_rp1[t*4+3] = ex; g_cur1[t*4+3] = ex; ex += l3;
    if (t == 1023) g_rp1[NCELL1] = ex;
    __syncthreads();

    // scan h2 (512) with first 512 threads
    int m0 = 0;
    if (t < 512) m0 = h2[t];
    ss[t] = m0;
    __syncthreads();
    for (int off = 1; off < 512; off <<= 1) {
        int v = (t >= off && t < 512) ? ss[t - off] : 0;
        __syncthreads();
        if (t < 512) ss[t] += v;
        __syncthreads();
    }
    if (t < 512) {
        int ex2 = (t == 0) ? 0 : ss[t - 1];
        g_rp2[t] = ex2; g_cur2[t] = ex2;
        if (t == 511) g_rp2[D_OUT] = ex2 + m0;
    }
}

// ---------------- prep 2/3: scatter edges into CSR ---------------------------
__global__ void k_scat1(const float* __restrict__ w1, const int* __restrict__ rows1,
                        const int* __restrict__ cols1) {
    int e = blockIdx.x * blockDim.x + threadIdx.x;
    if (e < NNZ1) {
        int c    = cols1[e];
        int cell = (c >> 11) * D_HID + rows1[e];
        int p    = atomicAdd(&g_cur1[cell], 1);
        g_e1[p]  = make_float2(w1[e], __int_as_float((c & 2047) * 2)); // fp16 byteoff
    }
}

__global__ void k_scat2(const float* __restrict__ w2, const int* __restrict__ rows2,
                        const int* __restrict__ cols2) {
    int e = blockIdx.x * blockDim.x + threadIdx.x;
    if (e < NNZ2) {
        int p   = atomicAdd(&g_cur2[rows2[e]], 1);
        g_e2[p] = make_float2(w2[e], __int_as_float(cols2[e] * (HS_STRIDE * 2)));
    }
}

// ---------------- layer 1: h = sigmoid(W1 x + b1) ----------------------------
// Block = 32 batches (lane = batch). Warp owns 32 rows per row-half.
// xs[batch][localcol] fp16, stride 2050 halves (odd word stride) ->
// gather addr = xs + lane*4100 + byteoff : banks (lane + word) % 32, 1 wavefront.
// Edge reads: uniform across warp (1 line), streamed with unroll-2 MLP.
__global__ __launch_bounds__(1024, 1)
void k_l1(const float* __restrict__ x, const float* __restrict__ b1) {
    extern __shared__ __half xs[];           // [32][XS_STRIDE] = 131200 B
    const int tid  = threadIdx.x;
    const int w    = tid >> 5;
    const int lane = tid & 31;
    const int b0   = blockIdx.x * 32;
    const char* xl = reinterpret_cast<const char*>(xs) + lane * (XS_STRIDE * 2);

    #pragma unroll 1
    for (int rp = 0; rp < 2; rp++) {
        const int row0 = rp * 1024 + w * 32;
        float acc[32];
        #pragma unroll
        for (int j = 0; j < 32; j++) acc[j] = __ldg(b1 + row0 + j);

        #pragma unroll 1
        for (int xp = 0; xp < NPH; xp++) {
            __syncthreads();
            {   // stage phase: warp w loads batch b0+w, fp32 -> fp16.
                // NOTE: 4-byte half2 stores only — warp base w*4100 B is
                // 4-mod-8 for odd w, so 8-byte stores would trap (R5 bug).
                const float4* xr = reinterpret_cast<const float4*>(
                    x + (size_t)(b0 + w) * D_IN + xp * PHC);
                __half2* xw = reinterpret_cast<__half2*>(xs + w * XS_STRIDE);
                #pragma unroll
                for (int it = 0; it < 16; it++) {
                    float4 v = __ldg(xr + it * 32 + lane);
                    int    wi = (it * 32 + lane) * 2;
                    xw[wi]     = __floats2half2_rn(v.x, v.y);
                    xw[wi + 1] = __floats2half2_rn(v.z, v.w);
                }
            }
            __syncthreads();

            #pragma unroll
            for (int j = 0; j < 32; j++) {
                const int cell = xp * D_HID + row0 + j;
                int p  = __ldg(&g_rp1[cell]);
                const int p1 = __ldg(&g_rp1[cell + 1]);
                float a = acc[j];
                for (; p + 2 <= p1; p += 2) {           // 2 edges in flight
                    float2 E0 = __ldg(&g_e1[p]);
                    float2 E1 = __ldg(&g_e1[p + 1]);
                    a += E0.x * __half2float(*reinterpret_cast<const __half*>(
                                    xl + __float_as_int(E0.y)));
                    a += E1.x * __half2float(*reinterpret_cast<const __half*>(
                                    xl + __float_as_int(E1.y)));
                }
                if (p < p1) {
                    float2 E0 = __ldg(&g_e1[p]);
                    a += E0.x * __half2float(*reinterpret_cast<const __half*>(
                                    xl + __float_as_int(E0.y)));
                }
                acc[j] = a;
            }
        }

        // sigmoid -> coalesced 64B fp16 stores (h[row][batch])
        #pragma unroll
        for (int j = 0; j < 32; j++) {
            float s = __fdividef(1.0f, 1.0f + __expf(-acc[j]));
            g_h[(size_t)(row0 + j) * NBATCH + b0 + lane] = __float2half(s);
        }
    }
}

// ---------------- layer 2: out = W2 h + b2 -----------------------------------
// Whole h column-slice in smem: hs[row][batch], 34-half stride.
// Gather = 64B span -> always 1 wavefront; edges uniform streamed.
__global__ __launch_bounds__(1024, 1)
void k_l2(const float* __restrict__ b2, float* __restrict__ out) {
    extern __shared__ char smem[];
    __half* hs  = reinterpret_cast<__half*>(smem);                       // 139264 B
    float*  ost = reinterpret_cast<float*>(smem + D_HID * HS_STRIDE * 2); // 67584 B

    const int tid  = threadIdx.x;
    const int w    = tid >> 5;
    const int lane = tid & 31;
    const int b0   = blockIdx.x * 32;
    const char* hl = reinterpret_cast<const char*>(hs) + lane * 2;

    {   // stage: warp w rows [w*64, w*64+64), 2 rows per iter (16 lanes each)
        const int r  = w * 64 + (lane >> 4);
        const int li = lane & 15;
        #pragma unroll
        for (int k = 0; k < 32; k++) {
            int rr = r + k * 2;
            unsigned v = *reinterpret_cast<const unsigned*>(
                g_h + (size_t)rr * NBATCH + b0 + li * 2);
            *reinterpret_cast<unsigned*>(hs + rr * HS_STRIDE + li * 2) = v;
        }
    }
    __syncthreads();

    #pragma unroll
    for (int j = 0; j < 16; j++) {
        const int r  = w * 16 + j;
        int p        = __ldg(&g_rp2[r]);
        const int p1 = __ldg(&g_rp2[r + 1]);
        float a = __ldg(b2 + r);
        for (; p + 2 <= p1; p += 2) {
            float2 E0 = __ldg(&g_e2[p]);
            float2 E1 = __ldg(&g_e2[p + 1]);
            a += E0.x * __half2float(*reinterpret_cast<const __half*>(
                            hl + __float_as_int(E0.y)));
            a += E1.x * __half2float(*reinterpret_cast<const __half*>(
                            hl + __float_as_int(E1.y)));
        }
        if (p < p1) {
            float2 E0 = __ldg(&g_e2[p]);
            a += E0.x * __half2float(*reinterpret_cast<const __half*>(
                            hl + __float_as_int(E0.y)));
        }
        ost[r * 33 + lane] = a;          // banks (r+lane)%32, conflict-free
    }
    __syncthreads();

    #pragma unroll
    for (int it = 0; it < 16; it++) {    // coalesced output copy
        int idx = it * 1024 + tid;
        int b = idx >> 9, r = idx & 511;
        out[(size_t)(b0 + b) * D_OUT + r] = ost[r * 33 + b];
    }
}

// ---------------- launch: 5 kernels, k_l1 at index 3 -------------------------
extern "C" void kernel_launch(void* const* d_in, const int* in_sizes, int n_in,
                              void* d_out, int out_size) {
    const float* x     = (const float*)d_in[0];
    const float* w1    = (const float*)d_in[1];
    const float* b1    = (const float*)d_in[2];
    const float* w2    = (const float*)d_in[3];
    const float* b2    = (const float*)d_in[4];
    const int*   rows1 = (const int*)d_in[5];
    const int*   cols1 = (const int*)d_in[6];
    const int*   rows2 = (const int*)d_in[7];
    const int*   cols2 = (const int*)d_in[8];
    float*       out   = (float*)d_out;

    k_prep<<<1, 1024>>>(rows1, cols1, rows2);
    k_scat1<<<NNZ1 / 256, 256>>>(w1, rows1, cols1);
    k_scat2<<<NNZ2 / 256, 256>>>(w2, rows2, cols2);

    const int SMEM1 = 32 * XS_STRIDE * 2;                         // 131200
    const int SMEM2 = D_HID * HS_STRIDE * 2 + D_OUT * 33 * 4;     // 206848
    cudaFuncSetAttribute(k_l1, cudaFuncAttributeMaxDynamicSharedMemorySize, SMEM1);
    cudaFuncSetAttribute(k_l2, cudaFuncAttributeMaxDynamicSharedMemorySize, SMEM2);
    k_l1<<<NBATCH / 32, 1024, SMEM1>>>(x, b1);
    k_l2<<<NBATCH / 32, 1024, SMEM2>>>(b2, out);
}

// round 7
// speedup vs baseline: 1.6795x; 1.0460x over previous
#include <cuda_runtime.h>
#include <cuda_fp16.h>

// Problem constants
#define D_IN    4096
#define D_HID   2048
#define D_OUT   512
#define NBATCH  8192
#define NNZ1    32768
#define NNZ2    8192
#define NPH     2
#define PHC     2048                  // x cols per phase
#define NCELL1  (NPH * D_HID)         // 4096 (cell = phase*D_HID + row)
#define XS_STRIDE 2050                // halves per batch row; 1025 words (odd) -> 1-wf gather
#define E1CAP   (NNZ1 + NCELL1)       // padded edge capacity
#define E2CAP   (NNZ2 + D_OUT)

// ---------------- scratch (__device__ globals) -------------------------------
__device__ __align__(16) float2 g_e1[E1CAP];   // CSR edges {w, __int_as_float(byteoff)}
__device__ __align__(16) float2 g_e2[E2CAP];
__device__ int    g_rp1[NCELL1 + 1];           // padded-even CSR starts (16B-aligned)
__device__ int    g_rp2[D_OUT + 1];
__device__ int    g_cur1[NCELL1];
__device__ int    g_cur2[D_OUT];
__device__ float  g_p[(size_t)D_HID * NBATCH]; // phase-0 partials, 64 MB (L2-resident/block)
__device__ __half g_h[(size_t)D_HID * NBATCH]; // h[row][batch], 32 MB

// ---------------- prep: hist + padded scan + pad-slot zero, ONE block --------
__global__ __launch_bounds__(1024, 1)
void k_prep(const int* __restrict__ rows1, const int* __restrict__ cols1,
            const int* __restrict__ rows2) {
    __shared__ int h1[NCELL1];
    __shared__ int h2[D_OUT];
    __shared__ int ss[1024];
    const int t = threadIdx.x;

    for (int i = t; i < NCELL1; i += 1024) h1[i] = 0;
    for (int i = t; i < D_OUT;  i += 1024) h2[i] = 0;
    __syncthreads();
    for (int e = t; e < NNZ1; e += 1024) {
        int cell = (__ldg(cols1 + e) >> 11) * D_HID + __ldg(rows1 + e);
        atomicAdd(&h1[cell], 1);
    }
    for (int e = t; e < NNZ2; e += 1024) atomicAdd(&h2[__ldg(rows2 + e)], 1);
    __syncthreads();

    // padded scan of h1 (4096 = 4/thread); padded len = (n+1)&~1 (even)
    int r0 = h1[t*4], r1 = h1[t*4+1], r2 = h1[t*4+2], r3 = h1[t*4+3];
    int p0 = (r0+1)&~1, p1 = (r1+1)&~1, p2 = (r2+1)&~1, p3 = (r3+1)&~1;
    ss[t] = p0 + p1 + p2 + p3;
    __syncthreads();
    for (int off = 1; off < 1024; off <<= 1) {
        int v = (t >= off) ? ss[t - off] : 0;
        __syncthreads();
        ss[t] += v;
        __syncthreads();
    }
    int ex = (t == 0) ? 0 : ss[t - 1];
    const float2 zed = make_float2(0.0f, 0.0f);
    g_rp1[t*4] = ex; g_cur1[t*4] = ex;
    if (r0 & 1) g_e1[ex + r0] = zed;
    ex += p0;
    g_rp1[t*4+1] = ex; g_cur1[t*4+1] = ex;
    if (r1 & 1) g_e1[ex + r1] = zed;
    ex += p1;
    g_rp1[t*4+2] = ex; g_cur1[t*4+2] = ex;
    if (r2 & 1) g_e1[ex + r2] = zed;
    ex += p2;
    g_rp1[t*4+3] = ex; g_cur1[t*4+3] = ex;
    if (r3 & 1) g_e1[ex + r3] = zed;
    ex += p3;
    if (t == 1023) g_rp1[NCELL1] = ex;
    __syncthreads();

    // padded scan of h2 (512, first 512 threads)
    int m0 = 0, q0 = 0;
    if (t < 512) { m0 = h2[t]; q0 = (m0+1)&~1; }
    ss[t] = q0;
    __syncthreads();
    for (int off = 1; off < 512; off <<= 1) {
        int v = (t >= off && t < 512) ? ss[t - off] : 0;
        __syncthreads();
        if (t < 512) ss[t] += v;
        __syncthreads();
    }
    if (t < 512) {
        int ex2 = (t == 0) ? 0 : ss[t - 1];
        g_rp2[t] = ex2; g_cur2[t] = ex2;
        if (m0 & 1) g_e2[ex2 + m0] = zed;
        if (t == 511) g_rp2[D_OUT] = ex2 + q0;
    }
}

// ---------------- scatter edges into padded CSR ------------------------------
__global__ void k_scat1(const float* __restrict__ w1, const int* __restrict__ rows1,
                        const int* __restrict__ cols1) {
    int e = blockIdx.x * blockDim.x + threadIdx.x;
    if (e < NNZ1) {
        int c    = cols1[e];
        int cell = (c >> 11) * D_HID + rows1[e];
        int p    = atomicAdd(&g_cur1[cell], 1);
        g_e1[p]  = make_float2(w1[e], __int_as_float((c & 2047) * 2)); // fp16 byteoff
    }
}

__global__ void k_scat2(const float* __restrict__ w2, const int* __restrict__ rows2,
                        const int* __restrict__ cols2) {
    int e = blockIdx.x * blockDim.x + threadIdx.x;
    if (e < NNZ2) {
        int p   = atomicAdd(&g_cur2[rows2[e]], 1);
        g_e2[p] = make_float2(w2[e], __int_as_float(cols2[e] * 2));    // fp16 byteoff
    }
}

// gather one fp16 from lane's tile row at byte offset o, widen to fp32
__device__ __forceinline__ float GX(const char* base, float o) {
    return __half2float(*reinterpret_cast<const __half*>(base + __float_as_int(o)));
}

// ---------------- layer 1: h = sigmoid(W1 x + b1) ----------------------------
// Block = 32 batches (lane = batch). Warp owns rows [w*64, w*64+64).
// Phase 0 stores fp32 partials to g_p (coalesced, L2-resident); phase 1 finishes.
// Edge stream: cells padded even + 16B-aligned -> LDG.128 = 2 edges; two
// adjacent rows interleaved -> 4 independent edges in flight.
__global__ __launch_bounds__(1024, 1)
void k_l1(const float* __restrict__ x, const float* __restrict__ b1) {
    extern __shared__ __half xs[];           // [32][XS_STRIDE] = 131200 B
    const int tid  = threadIdx.x;
    const int w    = tid >> 5;
    const int lane = tid & 31;
    const int b0   = blockIdx.x * 32;
    const char* xl = reinterpret_cast<const char*>(xs) + lane * (XS_STRIDE * 2);

    #pragma unroll 1
    for (int xp = 0; xp < NPH; xp++) {
        __syncthreads();
        {   // stage phase xp: warp w loads batch b0+w, fp32 -> fp16 (STS.32 only:
            // warp base w*4100 B is 4-mod-8 for odd w).
            const float4* xr = reinterpret_cast<const float4*>(
                x + (size_t)(b0 + w) * D_IN + xp * PHC);
            __half2* xw = reinterpret_cast<__half2*>(xs + w * XS_STRIDE);
            #pragma unroll
            for (int it = 0; it < 16; it++) {
                float4 v  = __ldg(xr + it * 32 + lane);
                int    wi = (it * 32 + lane) * 2;
                xw[wi]     = __floats2half2_rn(v.x, v.y);
                xw[wi + 1] = __floats2half2_rn(v.z, v.w);
            }
        }
        __syncthreads();

        const int rbase = w * 64;
        #pragma unroll 1
        for (int j = 0; j < 64; j += 2) {
            const int ra = rbase + j;
            const int ca = xp * D_HID + ra;
            const int pa = __ldg(&g_rp1[ca]);
            const int qa = __ldg(&g_rp1[ca + 1]);
            const int qb = __ldg(&g_rp1[ca + 2]);
            float a0, a1;
            if (xp == 0) {
                a0 = __ldg(b1 + ra);
                a1 = __ldg(b1 + ra + 1);
            } else {                    // plain loads (same-thread RAW with phase 0)
                a0 = g_p[(size_t)ra * NBATCH + b0 + lane];
                a1 = g_p[(size_t)(ra + 1) * NBATCH + b0 + lane];
            }
            const float4* Ea = reinterpret_cast<const float4*>(g_e1 + pa);
            const float4* Eb = reinterpret_cast<const float4*>(g_e1 + qa);
            const int ia = (qa - pa) >> 1;
            const int ib = (qb - qa) >> 1;
            const int m  = min(ia, ib);
            #pragma unroll 2
            for (int i = 0; i < m; i++) {
                float4 A = __ldg(Ea + i);
                float4 B = __ldg(Eb + i);
                a0 += A.x * GX(xl, A.y);
                a0 += A.z * GX(xl, A.w);
                a1 += B.x * GX(xl, B.y);
                a1 += B.z * GX(xl, B.w);
            }
            for (int i = m; i < ia; i++) {
                float4 A = __ldg(Ea + i);
                a0 += A.x * GX(xl, A.y);
                a0 += A.z * GX(xl, A.w);
            }
            for (int i = m; i < ib; i++) {
                float4 B = __ldg(Eb + i);
                a1 += B.x * GX(xl, B.y);
                a1 += B.z * GX(xl, B.w);
            }
            if (xp == 0) {
                g_p[(size_t)ra * NBATCH + b0 + lane]       = a0;
                g_p[(size_t)(ra + 1) * NBATCH + b0 + lane] = a1;
            } else {
                float s0 = __fdividef(1.0f, 1.0f + __expf(-a0));
                float s1 = __fdividef(1.0f, 1.0f + __expf(-a1));
                g_h[(size_t)ra * NBATCH + b0 + lane]       = __float2half(s0);
                g_h[(size_t)(ra + 1) * NBATCH + b0 + lane] = __float2half(s1);
            }
        }
    }
}

// ---------------- layer 2: out = W2 h + b2 -----------------------------------
// hs[batch][hid] fp16, odd-word stride -> 1-wf gather AND conflict-free
// transpose staging (STS.U16: word = lane*1025 + r/2, distinct per lane).
__global__ __launch_bounds__(1024, 1)
void k_l2(const float* __restrict__ b2, float* __restrict__ out) {
    extern __shared__ char smem[];
    __half* hs  = reinterpret_cast<__half*>(smem);                      // 131200 B
    float*  ost = reinterpret_cast<float*>(smem + 32 * XS_STRIDE * 2);  // 512*33*4

    const int tid  = threadIdx.x;
    const int w    = tid >> 5;
    const int lane = tid & 31;
    const int b0   = blockIdx.x * 32;
    const char* hl = reinterpret_cast<const char*>(hs) + lane * (XS_STRIDE * 2);

    {   // stage + transpose: warp w covers rows [w*64, w*64+64)
        #pragma unroll 4
        for (int k = 0; k < 64; k++) {
            int r = w * 64 + k;
            __half v = __ldg(&g_h[(size_t)r * NBATCH + b0 + lane]);  // 64B coalesced
            hs[lane * XS_STRIDE + r] = v;                            // 1-wf STS.U16
        }
    }
    __syncthreads();

    #pragma unroll 1
    for (int j = 0; j < 16; j += 2) {
        const int ra = w * 16 + j;
        const int pa = __ldg(&g_rp2[ra]);
        const int qa = __ldg(&g_rp2[ra + 1]);
        const int qb = __ldg(&g_rp2[ra + 2]);
        float a0 = __ldg(b2 + ra);
        float a1 = __ldg(b2 + ra + 1);
        const float4* Ea = reinterpret_cast<const float4*>(g_e2 + pa);
        const float4* Eb = reinterpret_cast<const float4*>(g_e2 + qa);
        const int ia = (qa - pa) >> 1;
        const int ib = (qb - qa) >> 1;
        const int m  = min(ia, ib);
        #pragma unroll 2
        for (int i = 0; i < m; i++) {
            float4 A = __ldg(Ea + i);
            float4 B = __ldg(Eb + i);
            a0 += A.x * GX(hl, A.y);
            a0 += A.z * GX(hl, A.w);
            a1 += B.x * GX(hl, B.y);
            a1 += B.z * GX(hl, B.w);
        }
        for (int i = m; i < ia; i++) {
            float4 A = __ldg(Ea + i);
            a0 += A.x * GX(hl, A.y);
            a0 += A.z * GX(hl, A.w);
        }
        for (int i = m; i < ib; i++) {
            float4 B = __ldg(Eb + i);
            a1 += B.x * GX(hl, B.y);
            a1 += B.z * GX(hl, B.w);
        }
        ost[ra * 33 + lane]       = a0;   // banks (ra+lane)%32, conflict-free
        ost[(ra + 1) * 33 + lane] = a1;
    }
    __syncthreads();

    #pragma unroll
    for (int it = 0; it < 16; it++) {     // coalesced output copy
        int idx = it * 1024 + tid;
        int b = idx >> 9, r = idx & 511;
        out[(size_t)(b0 + b) * D_OUT + r] = ost[r * 33 + b];
    }
}

// ---------------- launch: 5 kernels, k_l1 at index 3 (profiler slot) ---------
extern "C" void kernel_launch(void* const* d_in, const int* in_sizes, int n_in,
                              void* d_out, int out_size) {
    const float* x     = (const float*)d_in[0];
    const float* w1    = (const float*)d_in[1];
    const float* b1    = (const float*)d_in[2];
    const float* w2    = (const float*)d_in[3];
    const float* b2    = (const float*)d_in[4];
    const int*   rows1 = (const int*)d_in[5];
    const int*   cols1 = (const int*)d_in[6];
    const int*   rows2 = (const int*)d_in[7];
    const int*   cols2 = (const int*)d_in[8];
    float*       out   = (float*)d_out;

    k_prep<<<1, 1024>>>(rows1, cols1, rows2);
    k_scat1<<<NNZ1 / 256, 256>>>(w1, rows1, cols1);
    k_scat2<<<NNZ2 / 256, 256>>>(w2, rows2, cols2);

    const int SMEM1 = 32 * XS_STRIDE * 2;                      // 131200
    const int SMEM2 = 32 * XS_STRIDE * 2 + D_OUT * 33 * 4;     // 198784
    cudaFuncSetAttribute(k_l1, cudaFuncAttributeMaxDynamicSharedMemorySize, SMEM1);
    cudaFuncSetAttribute(k_l2, cudaFuncAttributeMaxDynamicSharedMemorySize, SMEM2);
    k_l1<<<NBATCH / 32, 1024, SMEM1>>>(x, b1);
    k_l2<<<NBATCH / 32, 1024, SMEM2>>>(b2, out);
}

// round 8
// speedup vs baseline: 2.0071x; 1.1950x over previous
#include <cuda_runtime.h>
#include <cuda_fp16.h>

// Problem constants
#define D_IN    4096
#define D_HID   2048
#define D_OUT   512
#define NBATCH  8192
#define NNZ1    32768
#define NNZ2    8192
#define TB      64                    // batches per block; lane = 2 batches
#define NPH1    4                     // layer-1 col phases (1024 each)
#define NPH2    2                     // layer-2 col phases (1024 each)
#define PC1     1024
#define NCELL1  (NPH1 * D_HID)        // 8192
#define NCELL2  (NPH2 * D_OUT)        // 1024
#define E1CAP   (NNZ1 + NCELL1)
#define E2CAP   (NNZ2 + NCELL2)
#define CSTR    33                    // u32 words per tile column (132B)

// ---------------- scratch (__device__ globals) -------------------------------
__device__ __align__(16) float2 g_e1[E1CAP];  // CSR edges {w, __int_as_float(byteoff)}
__device__ __align__(16) float2 g_e2[E2CAP];
__device__ int      g_rp1[NCELL1 + 1];        // even (16B-aligned) CSR starts
__device__ int      g_rp2[NCELL2 + 1];
__device__ int      g_cur1[NCELL1];
__device__ int      g_cur2[NCELL2];
__device__ unsigned g_p[(size_t)D_HID * (NBATCH / 2)];  // fp16x2 partials [row][bpair]
__device__ __half   g_h[(size_t)D_HID * NBATCH];        // h[row][batch]

// ---------------- prep: hist + padded scans, ONE block -----------------------
__global__ __launch_bounds__(1024, 1)
void k_prep(const int* __restrict__ rows1, const int* __restrict__ cols1,
            const int* __restrict__ rows2, const int* __restrict__ cols2) {
    __shared__ int h1[NCELL1];    // 32 KB
    __shared__ int h2[NCELL2];
    __shared__ int ss[1024];
    const int t = threadIdx.x;

    for (int i = t; i < NCELL1; i += 1024) h1[i] = 0;
    for (int i = t; i < NCELL2; i += 1024) h2[i] = 0;
    __syncthreads();
    for (int e = t; e < NNZ1; e += 1024) {
        int c = __ldg(cols1 + e);
        atomicAdd(&h1[(c >> 10) * D_HID + __ldg(rows1 + e)], 1);
    }
    for (int e = t; e < NNZ2; e += 1024) {
        int c = __ldg(cols2 + e);
        atomicAdd(&h2[(c >> 10) * D_OUT + __ldg(rows2 + e)], 1);
    }
    __syncthreads();

    // padded-even scan of h1 (8 cells/thread)
    int r[8], p[8], s = 0;
    #pragma unroll
    for (int k = 0; k < 8; k++) {
        r[k] = h1[t * 8 + k];
        p[k] = (r[k] + 1) & ~1;
        s += p[k];
    }
    ss[t] = s;
    __syncthreads();
    for (int off = 1; off < 1024; off <<= 1) {
        int v = (t >= off) ? ss[t - off] : 0;
        __syncthreads();
        ss[t] += v;
        __syncthreads();
    }
    int ex = (t == 0) ? 0 : ss[t - 1];
    const float2 zed = make_float2(0.0f, 0.0f);
    #pragma unroll
    for (int k = 0; k < 8; k++) {
        g_rp1[t * 8 + k] = ex;
        g_cur1[t * 8 + k] = ex;
        if (r[k] & 1) g_e1[ex + r[k]] = zed;     // zero the pad slot
        ex += p[k];
    }
    if (t == 1023) g_rp1[NCELL1] = ex;
    __syncthreads();

    // padded-even scan of h2 (1 cell/thread)
    int m = h2[t];
    int q = (m + 1) & ~1;
    ss[t] = q;
    __syncthreads();
    for (int off = 1; off < 1024; off <<= 1) {
        int v = (t >= off) ? ss[t - off] : 0;
        __syncthreads();
        ss[t] += v;
        __syncthreads();
    }
    int ex2 = (t == 0) ? 0 : ss[t - 1];
    g_rp2[t] = ex2;
    g_cur2[t] = ex2;
    if (m & 1) g_e2[ex2 + m] = zed;
    if (t == 1023) g_rp2[NCELL2] = ex2 + q;
}

// ---------------- scatter edges into padded CSR ------------------------------
__global__ void k_scat1(const float* __restrict__ w1, const int* __restrict__ rows1,
                        const int* __restrict__ cols1) {
    int e = blockIdx.x * blockDim.x + threadIdx.x;
    if (e < NNZ1) {
        int c    = cols1[e];
        int cell = (c >> 10) * D_HID + rows1[e];
        int p    = atomicAdd(&g_cur1[cell], 1);
        g_e1[p]  = make_float2(w1[e], __int_as_float((c & 1023) * (CSTR * 4)));
    }
}

__global__ void k_scat2(const float* __restrict__ w2, const int* __restrict__ rows2,
                        const int* __restrict__ cols2) {
    int e = blockIdx.x * blockDim.x + threadIdx.x;
    if (e < NNZ2) {
        int c    = cols2[e];
        int cell = (c >> 10) * D_OUT + rows2[e];
        int p    = atomicAdd(&g_cur2[cell], 1);
        g_e2[p]  = make_float2(w2[e], __int_as_float((c & 1023) * (CSTR * 4)));
    }
}

// gather half2 (2 batches) at byte offset o from lane base, widen to float2
__device__ __forceinline__ float2 GX2(const char* base, float o) {
    return __half22float2(*reinterpret_cast<const __half2*>(base + __float_as_int(o)));
}

// ---------------- layer 1: h = sigmoid(W1 x + b1) ----------------------------
// Block = 64 batches, lane = batch pair. Tile xs[col][bpair] u32 words,
// col stride CSTR=33 words: gather word = col*33 + lane -> banks (col+lane)%32,
// always 1 wavefront; staging word = col*33 + w, lanes sweep col -> 1 wf.
// Warp owns rows [w*64, w*64+64). Partials bounce via fp16x2 g_p (3 boundaries).
__global__ __launch_bounds__(1024, 1)
void k_l1(const float* __restrict__ x, const float* __restrict__ b1) {
    extern __shared__ __half xs[];       // PC1 * CSTR u32 = 135168 B
    unsigned* xw = reinterpret_cast<unsigned*>(xs);
    const int tid  = threadIdx.x;
    const int w    = tid >> 5;
    const int lane = tid & 31;
    const int b0   = blockIdx.x * TB;
    const char* xl = reinterpret_cast<const char*>(xs) + lane * 4;
    const int bp0  = b0 >> 1;            // global batch-pair base

    #pragma unroll 1
    for (int xp = 0; xp < NPH1; xp++) {
        __syncthreads();
        {   // stage: warp w converts batches (b0+2w, b0+2w+1) for this phase
            const float* xrA = x + (size_t)(b0 + 2 * w) * D_IN + xp * PC1;
            const float* xrB = xrA + D_IN;
            #pragma unroll
            for (int it = 0; it < 32; it++) {
                int c = it * 32 + lane;
                __half2 hv = __floats2half2_rn(__ldg(xrA + c), __ldg(xrB + c));
                xw[c * CSTR + w] = *reinterpret_cast<unsigned*>(&hv);
            }
        }
        __syncthreads();

        const int rbase = w * 64;
        #pragma unroll 1
        for (int j = 0; j < 64; j += 2) {
            const int row  = rbase + j;
            const int cell = xp * D_HID + row;
            int2 pq = *reinterpret_cast<const int2*>(&g_rp1[cell]);
            const int p2 = __ldg(&g_rp1[cell + 2]);
            float a00, a01, a10, a11;
            if (xp == 0) {
                float ba = __ldg(b1 + row);
                float bb = __ldg(b1 + row + 1);
                a00 = a01 = ba;
                a10 = a11 = bb;
            } else {
                unsigned u0 = g_p[(size_t)row * (NBATCH / 2) + bp0 + lane];
                unsigned u1 = g_p[(size_t)(row + 1) * (NBATCH / 2) + bp0 + lane];
                float2 f0 = __half22float2(*reinterpret_cast<__half2*>(&u0));
                float2 f1 = __half22float2(*reinterpret_cast<__half2*>(&u1));
                a00 = f0.x; a01 = f0.y;
                a10 = f1.x; a11 = f1.y;
            }
            const float4* Ea = reinterpret_cast<const float4*>(g_e1 + pq.x);
            const float4* Eb = reinterpret_cast<const float4*>(g_e1 + pq.y);
            const int ia = (pq.y - pq.x) >> 1;
            const int ib = (p2 - pq.y) >> 1;
            const int m  = min(ia, ib);
            #pragma unroll 2
            for (int i = 0; i < m; i++) {
                float4 A = __ldg(Ea + i);
                float4 B = __ldg(Eb + i);
                float2 f;
                f = GX2(xl, A.y); a00 += A.x * f.x; a01 += A.x * f.y;
                f = GX2(xl, A.w); a00 += A.z * f.x; a01 += A.z * f.y;
                f = GX2(xl, B.y); a10 += B.x * f.x; a11 += B.x * f.y;
                f = GX2(xl, B.w); a10 += B.z * f.x; a11 += B.z * f.y;
            }
            for (int i = m; i < ia; i++) {
                float4 A = __ldg(Ea + i);
                float2 f;
                f = GX2(xl, A.y); a00 += A.x * f.x; a01 += A.x * f.y;
                f = GX2(xl, A.w); a00 += A.z * f.x; a01 += A.z * f.y;
            }
            for (int i = m; i < ib; i++) {
                float4 B = __ldg(Eb + i);
                float2 f;
                f = GX2(xl, B.y); a10 += B.x * f.x; a11 += B.x * f.y;
                f = GX2(xl, B.w); a10 += B.z * f.x; a11 += B.z * f.y;
            }
            if (xp < NPH1 - 1) {
                __half2 h0 = __floats2half2_rn(a00, a01);
                __half2 h1v = __floats2half2_rn(a10, a11);
                g_p[(size_t)row * (NBATCH / 2) + bp0 + lane]       =
                    *reinterpret_cast<unsigned*>(&h0);
                g_p[(size_t)(row + 1) * (NBATCH / 2) + bp0 + lane] =
                    *reinterpret_cast<unsigned*>(&h1v);
            } else {
                float s00 = __fdividef(1.0f, 1.0f + __expf(-a00));
                float s01 = __fdividef(1.0f, 1.0f + __expf(-a01));
                float s10 = __fdividef(1.0f, 1.0f + __expf(-a10));
                float s11 = __fdividef(1.0f, 1.0f + __expf(-a11));
                __half2 h0 = __floats2half2_rn(s00, s01);
                __half2 h1v = __floats2half2_rn(s10, s11);
                *reinterpret_cast<unsigned*>(
                    &g_h[(size_t)row * NBATCH + b0 + 2 * lane]) =
                    *reinterpret_cast<unsigned*>(&h0);
                *reinterpret_cast<unsigned*>(
                    &g_h[(size_t)(row + 1) * NBATCH + b0 + 2 * lane]) =
                    *reinterpret_cast<unsigned*>(&h1v);
            }
        }
    }
}

// ---------------- layer 2: out = W2 h + b2 -----------------------------------
// Same tile scheme; warp owns 16 rows, acc (32 fp32) persists across 2 phases.
#define OSTR 67   // floats per out row in smem stage
__global__ __launch_bounds__(1024, 1)
void k_l2(const float* __restrict__ b2, float* __restrict__ out) {
    extern __shared__ __half hsm[];
    unsigned* hw = reinterpret_cast<unsigned*>(hsm);
    const int tid  = threadIdx.x;
    const int w    = tid >> 5;
    const int lane = tid & 31;
    const int b0   = blockIdx.x * TB;
    const char* hl = reinterpret_cast<const char*>(hsm) + lane * 4;

    float a[32];
    #pragma unroll
    for (int j = 0; j < 16; j++) {
        float b = __ldg(b2 + w * 16 + j);
        a[2 * j] = b;
        a[2 * j + 1] = b;
    }

    #pragma unroll 1
    for (int hp = 0; hp < NPH2; hp++) {
        __syncthreads();
        {   // stage: warp w covers local cols [w*32, w*32+32)
            #pragma unroll
            for (int i = 0; i < 32; i++) {
                int c = w * 32 + i;
                unsigned v = __ldg(reinterpret_cast<const unsigned*>(
                    g_h + (size_t)(hp * PC1 + c) * NBATCH + b0 + 2 * lane));
                hw[c * CSTR + lane] = v;
            }
        }
        __syncthreads();

        #pragma unroll
        for (int j = 0; j < 16; j += 2) {
            const int row  = w * 16 + j;
            const int cell = hp * D_OUT + row;
            int2 pq = *reinterpret_cast<const int2*>(&g_rp2[cell]);
            const int p2 = __ldg(&g_rp2[cell + 2]);
            const float4* Ea = reinterpret_cast<const float4*>(g_e2 + pq.x);
            const float4* Eb = reinterpret_cast<const float4*>(g_e2 + pq.y);
            const int ia = (pq.y - pq.x) >> 1;
            const int ib = (p2 - pq.y) >> 1;
            const int m  = min(ia, ib);
            float a00 = a[2*j], a01 = a[2*j+1], a10 = a[2*j+2], a11 = a[2*j+3];
            #pragma unroll 2
            for (int i = 0; i < m; i++) {
                float4 A = __ldg(Ea + i);
                float4 B = __ldg(Eb + i);
                float2 f;
                f = GX2(hl, A.y); a00 += A.x * f.x; a01 += A.x * f.y;
                f = GX2(hl, A.w); a00 += A.z * f.x; a01 += A.z * f.y;
                f = GX2(hl, B.y); a10 += B.x * f.x; a11 += B.x * f.y;
                f = GX2(hl, B.w); a10 += B.z * f.x; a11 += B.z * f.y;
            }
            for (int i = m; i < ia; i++) {
                float4 A = __ldg(Ea + i);
                float2 f;
                f = GX2(hl, A.y); a00 += A.x * f.x; a01 += A.x * f.y;
                f = GX2(hl, A.w); a00 += A.z * f.x; a01 += A.z * f.y;
            }
            for (int i = m; i < ib; i++) {
                float4 B = __ldg(Eb + i);
                float2 f;
                f = GX2(hl, B.y); a10 += B.x * f.x; a11 += B.x * f.y;
                f = GX2(hl, B.w); a10 += B.z * f.x; a11 += B.z * f.y;
            }
            a[2*j] = a00; a[2*j+1] = a01; a[2*j+2] = a10; a[2*j+3] = a11;
        }
    }

    // stage out (overlay tile) then coalesced copy
    __syncthreads();
    float* ost = reinterpret_cast<float*>(hsm);
    #pragma unroll
    for (int j = 0; j < 16; j++) {
        int row = w * 16 + j;
        ost[row * OSTR + 2 * lane]     = a[2 * j];       // scalar STS (8B-misaligned
        ost[row * OSTR + 2 * lane + 1] = a[2 * j + 1];   //  pairs for odd rows)
    }
    __syncthreads();
    #pragma unroll
    for (int it = 0; it < 32; it++) {
        int idx = it * 1024 + tid;
        int b = idx >> 9;
        int r = idx & 511;
        out[(size_t)(b0 + b) * D_OUT + r] = ost[r * OSTR + b];
    }
}

// ---------------- launch: 5 kernels, k_l1 at index 3 (profiler slot) ---------
extern "C" void kernel_launch(void* const* d_in, const int* in_sizes, int n_in,
                              void* d_out, int out_size) {
    const float* x     = (const float*)d_in[0];
    const float* w1    = (const float*)d_in[1];
    const float* b1    = (const float*)d_in[2];
    const float* w2    = (const float*)d_in[3];
    const float* b2    = (const float*)d_in[4];
    const int*   rows1 = (const int*)d_in[5];
    const int*   cols1 = (const int*)d_in[6];
    const int*   rows2 = (const int*)d_in[7];
    const int*   cols2 = (const int*)d_in[8];
    float*       out   = (float*)d_out;

    k_prep<<<1, 1024>>>(rows1, cols1, rows2, cols2);
    k_scat1<<<NNZ1 / 256, 256>>>(w1, rows1, cols1);
    k_scat2<<<NNZ2 / 256, 256>>>(w2, rows2, cols2);

    const int SMEM1 = PC1 * CSTR * 4;                         // 135168
    const int SMEM2 = D_OUT * OSTR * 4;                       // 137216 (>= tile)
    cudaFuncSetAttribute(k_l1, cudaFuncAttributeMaxDynamicSharedMemorySize, SMEM1);
    cudaFuncSetAttribute(k_l2, cudaFuncAttributeMaxDynamicSharedMemorySize, SMEM2);
    k_l1<<<NBATCH / TB, 1024, SMEM1>>>(x, b1);
    k_l2<<<NBATCH / TB, 1024, SMEM2>>>(b2, out);
}

// round 9
// speedup vs baseline: 2.2390x; 1.1155x over previous
#include <cuda_runtime.h>
#include <cuda_fp16.h>

// Problem constants
#define D_IN    4096
#define D_HID   2048
#define D_OUT   512
#define NBATCH  8192
#define NNZ1    32768
#define NNZ2    8192
#define TB      64                    // batches per block; lane = 2 batches
#define NPH1    4                     // layer-1 col phases (1024 each)
#define NPH2    2                     // layer-2 col phases (1024 each)
#define PC1     1024
#define NCELL1  (NPH1 * D_HID)        // 8192
#define NCELL2  (NPH2 * D_OUT)        // 1024
#define E1CAP   (NNZ1 + NCELL1)
#define E2CAP   (NNZ2 + NCELL2)
#define CSTR    33                    // u32 words per tile column
#define SUBT    8448                  // words per (col&3) sub-tile (k_l1 swizzle)
#define NBP     (NBATCH / 2)

// ---------------- scratch (__device__ globals) -------------------------------
__device__ __align__(16) float2 g_e1[E1CAP];  // {w_half2_bits, byteoff}
__device__ __align__(16) float2 g_e2[E2CAP];  // {w_fp32, byteoff}
__device__ __align__(16) int g_rp1[NCELL1 + 4];
__device__ __align__(16) int g_rp2[NCELL2 + 2];
__device__ int      g_cur1[NCELL1];
__device__ int      g_cur2[NCELL2];
__device__ unsigned g_p[(size_t)D_HID * NBP]; // fp16x2 partials [row][bpair]
__device__ __half   g_h[(size_t)D_HID * NBATCH];

// ---------------- helpers ----------------------------------------------------
__device__ __forceinline__ __half2 F2H2(float f) {
    unsigned u = __float_as_uint(f);
    return *reinterpret_cast<__half2*>(&u);
}
__device__ __forceinline__ __half2 LDS2(const char* base, float o) {
    return *reinterpret_cast<const __half2*>(base + __float_as_int(o));
}
__device__ __forceinline__ unsigned H2U(__half2 h) {
    return *reinterpret_cast<unsigned*>(&h);
}
__device__ __forceinline__ __half2 U2H(unsigned u) {
    return *reinterpret_cast<__half2*>(&u);
}
__device__ __forceinline__ float sigf(float v) {
    return __fdividef(1.0f, 1.0f + __expf(-v));
}
__device__ __forceinline__ float2 GX2(const char* base, float o) {
    return __half22float2(*reinterpret_cast<const __half2*>(base + __float_as_int(o)));
}

// ---------------- prep: hist + padded scans, ONE block -----------------------
__global__ __launch_bounds__(1024, 1)
void k_prep(const int* __restrict__ rows1, const int* __restrict__ cols1,
            const int* __restrict__ rows2, const int* __restrict__ cols2) {
    __shared__ int h1[NCELL1];
    __shared__ int h2[NCELL2];
    __shared__ int ss[1024];
    const int t = threadIdx.x;

    for (int i = t; i < NCELL1; i += 1024) h1[i] = 0;
    for (int i = t; i < NCELL2; i += 1024) h2[i] = 0;
    __syncthreads();
    for (int e = t; e < NNZ1; e += 1024) {
        int c = __ldg(cols1 + e);
        atomicAdd(&h1[(c >> 10) * D_HID + __ldg(rows1 + e)], 1);
    }
    for (int e = t; e < NNZ2; e += 1024) {
        int c = __ldg(cols2 + e);
        atomicAdd(&h2[(c >> 10) * D_OUT + __ldg(rows2 + e)], 1);
    }
    __syncthreads();

    int r[8], p[8], s = 0;
    #pragma unroll
    for (int k = 0; k < 8; k++) {
        r[k] = h1[t * 8 + k];
        p[k] = (r[k] + 1) & ~1;
        s += p[k];
    }
    ss[t] = s;
    __syncthreads();
    for (int off = 1; off < 1024; off <<= 1) {
        int v = (t >= off) ? ss[t - off] : 0;
        __syncthreads();
        ss[t] += v;
        __syncthreads();
    }
    int ex = (t == 0) ? 0 : ss[t - 1];
    const float2 zed = make_float2(0.0f, 0.0f);
    #pragma unroll
    for (int k = 0; k < 8; k++) {
        g_rp1[t * 8 + k] = ex;
        g_cur1[t * 8 + k] = ex;
        if (r[k] & 1) g_e1[ex + r[k]] = zed;
        ex += p[k];
    }
    if (t == 1023) g_rp1[NCELL1] = ex;
    __syncthreads();

    int m = h2[t];
    int q = (m + 1) & ~1;
    ss[t] = q;
    __syncthreads();
    for (int off = 1; off < 1024; off <<= 1) {
        int v = (t >= off) ? ss[t - off] : 0;
        __syncthreads();
        ss[t] += v;
        __syncthreads();
    }
    int ex2 = (t == 0) ? 0 : ss[t - 1];
    g_rp2[t] = ex2;
    g_cur2[t] = ex2;
    if (m & 1) g_e2[ex2 + m] = zed;
    if (t == 1023) g_rp2[NCELL2] = ex2 + q;
}

// ---------------- scatter edges into padded CSR ------------------------------
__global__ void k_scat1(const float* __restrict__ w1, const int* __restrict__ rows1,
                        const int* __restrict__ cols1) {
    int e = blockIdx.x * blockDim.x + threadIdx.x;
    if (e < NNZ1) {
        int c    = cols1[e];
        int cell = (c >> 10) * D_HID + rows1[e];
        int p    = atomicAdd(&g_cur1[cell], 1);
        int cl   = c & 1023;
        int soff = ((cl & 3) * SUBT + (cl >> 2) * CSTR) * 4;  // swizzled byteoff
        __half2 wp = __float2half2_rn(w1[e]);                 // {w, w} fp16
        g_e1[p] = make_float2(__uint_as_float(H2U(wp)), __int_as_float(soff));
    }
}

__global__ void k_scat2(const float* __restrict__ w2, const int* __restrict__ rows2,
                        const int* __restrict__ cols2) {
    int e = blockIdx.x * blockDim.x + threadIdx.x;
    if (e < NNZ2) {
        int c    = cols2[e];
        int cell = (c >> 10) * D_OUT + rows2[e];
        int p    = atomicAdd(&g_cur2[cell], 1);
        g_e2[p]  = make_float2(w2[e], __int_as_float((c & 1023) * (CSTR * 4)));
    }
}

// ---------------- layer 1 dual-row HFMA2 edge stream -------------------------
__device__ __forceinline__ void pair_l1(__half2& a0, __half2& a1,
                                        int p0, int p1, int p2, const char* xl) {
    const float4* Ea = reinterpret_cast<const float4*>(g_e1 + p0);
    const float4* Eb = reinterpret_cast<const float4*>(g_e1 + p1);
    const int ia = (p1 - p0) >> 1;
    const int ib = (p2 - p1) >> 1;
    const int m  = min(ia, ib);
    #pragma unroll 2
    for (int i = 0; i < m; i++) {
        float4 A = __ldg(Ea + i);
        float4 B = __ldg(Eb + i);
        a0 = __hfma2(F2H2(A.x), LDS2(xl, A.y), a0);
        a0 = __hfma2(F2H2(A.z), LDS2(xl, A.w), a0);
        a1 = __hfma2(F2H2(B.x), LDS2(xl, B.y), a1);
        a1 = __hfma2(F2H2(B.z), LDS2(xl, B.w), a1);
    }
    for (int i = m; i < ia; i++) {
        float4 A = __ldg(Ea + i);
        a0 = __hfma2(F2H2(A.x), LDS2(xl, A.y), a0);
        a0 = __hfma2(F2H2(A.z), LDS2(xl, A.w), a0);
    }
    for (int i = m; i < ib; i++) {
        float4 B = __ldg(Eb + i);
        a1 = __hfma2(F2H2(B.x), LDS2(xl, B.y), a1);
        a1 = __hfma2(F2H2(B.z), LDS2(xl, B.w), a1);
    }
}

// ---------------- layer 1: h = sigmoid(W1 x + b1) ----------------------------
// Block = 64 batches, lane = batch pair. Sub-tile swizzle: col stored at word
// s(col) = (col&3)*SUBT + (col>>2)*33; gather word s+lane -> banks q+lane,
// 1 wavefront; staging word q*33+w (+k*SUBT) -> banks lane+w, 1 wavefront,
// enabling float4 x loads. fp16x2 acc chain, bounce via g_p between phases.
__global__ __launch_bounds__(1024, 1)
void k_l1(const float* __restrict__ x, const float* __restrict__ b1) {
    extern __shared__ unsigned xw[];     // 4*SUBT words = 135168 B
    const int tid  = threadIdx.x;
    const int w    = tid >> 5;
    const int lane = tid & 31;
    const int b0   = blockIdx.x * TB;
    const char* xl = reinterpret_cast<const char*>(xw) + lane * 4;
    const int bp   = (b0 >> 1) + lane;

    #pragma unroll 1
    for (int xp = 0; xp < NPH1; xp++) {
        __syncthreads();
        {   // stage: warp w packs batches (b0+2w, b0+2w+1), float4 granules
            const float4* xrA = reinterpret_cast<const float4*>(
                x + (size_t)(b0 + 2 * w) * D_IN + xp * PC1);
            const float4* xrB = xrA + (D_IN / 4);
            #pragma unroll
            for (int it = 0; it < 8; it++) {
                int    q = it * 32 + lane;           // granule = col>>2
                float4 a = __ldg(xrA + q);
                float4 b = __ldg(xrB + q);
                unsigned* dst = xw + q * CSTR + w;
                dst[0]        = H2U(__floats2half2_rn(a.x, b.x));
                dst[SUBT]     = H2U(__floats2half2_rn(a.y, b.y));
                dst[2 * SUBT] = H2U(__floats2half2_rn(a.z, b.z));
                dst[3 * SUBT] = H2U(__floats2half2_rn(a.w, b.w));
            }
        }
        __syncthreads();

        const int rb = w * 64;
        const int cb = xp * D_HID + rb;
        #pragma unroll 1
        for (int j = 0; j < 64; j += 4) {          // 4-row groups
            int4 P  = *reinterpret_cast<const int4*>(&g_rp1[cb + j]);
            int  p4 = __ldg(&g_rp1[cb + j + 4]);
            __half2 a0, a1, a2, a3;
            if (xp == 0) {
                float4 bb = __ldg(reinterpret_cast<const float4*>(b1 + rb + j));
                a0 = __float2half2_rn(bb.x);
                a1 = __float2half2_rn(bb.y);
                a2 = __float2half2_rn(bb.z);
                a3 = __float2half2_rn(bb.w);
            } else {
                size_t pb = (size_t)(rb + j) * NBP + bp;
                a0 = U2H(g_p[pb]);
                a1 = U2H(g_p[pb + NBP]);
                a2 = U2H(g_p[pb + 2 * NBP]);
                a3 = U2H(g_p[pb + 3 * NBP]);
            }
            pair_l1(a0, a1, P.x, P.y, P.z, xl);
            pair_l1(a2, a3, P.z, P.w, p4, xl);
            if (xp < NPH1 - 1) {
                size_t pb = (size_t)(rb + j) * NBP + bp;
                g_p[pb]           = H2U(a0);
                g_p[pb + NBP]     = H2U(a1);
                g_p[pb + 2 * NBP] = H2U(a2);
                g_p[pb + 3 * NBP] = H2U(a3);
            } else {
                size_t hb = (size_t)(rb + j) * NBATCH + b0 + 2 * lane;
                float2 z;
                z = __half22float2(a0);
                *reinterpret_cast<unsigned*>(&g_h[hb]) =
                    H2U(__floats2half2_rn(sigf(z.x), sigf(z.y)));
                z = __half22float2(a1);
                *reinterpret_cast<unsigned*>(&g_h[hb + NBATCH]) =
                    H2U(__floats2half2_rn(sigf(z.x), sigf(z.y)));
                z = __half22float2(a2);
                *reinterpret_cast<unsigned*>(&g_h[hb + 2 * NBATCH]) =
                    H2U(__floats2half2_rn(sigf(z.x), sigf(z.y)));
                z = __half22float2(a3);
                *reinterpret_cast<unsigned*>(&g_h[hb + 3 * NBATCH]) =
                    H2U(__floats2half2_rn(sigf(z.x), sigf(z.y)));
            }
        }
    }
}

// ---------------- layer 2: out = W2 h + b2 (fp32 accumulation) ---------------
#define OSTR 67
__global__ __launch_bounds__(1024, 1)
void k_l2(const float* __restrict__ b2, float* __restrict__ out) {
    extern __shared__ __half hsm[];
    unsigned* hw = reinterpret_cast<unsigned*>(hsm);
    const int tid  = threadIdx.x;
    const int w    = tid >> 5;
    const int lane = tid & 31;
    const int b0   = blockIdx.x * TB;
    const char* hl = reinterpret_cast<const char*>(hsm) + lane * 4;

    float a[32];
    #pragma unroll
    for (int j = 0; j < 16; j++) {
        float b = __ldg(b2 + w * 16 + j);
        a[2 * j] = b;
        a[2 * j + 1] = b;
    }

    #pragma unroll 1
    for (int hp = 0; hp < NPH2; hp++) {
        __syncthreads();
        {   // stage: warp w covers local cols [w*32, w*32+32)
            #pragma unroll
            for (int i = 0; i < 32; i++) {
                int c = w * 32 + i;
                unsigned v = __ldg(reinterpret_cast<const unsigned*>(
                    g_h + (size_t)(hp * PC1 + c) * NBATCH + b0 + 2 * lane));
                hw[c * CSTR + lane] = v;
            }
        }
        __syncthreads();

        #pragma unroll
        for (int j = 0; j < 16; j += 2) {
            const int row  = w * 16 + j;
            const int cell = hp * D_OUT + row;
            int2 pq = *reinterpret_cast<const int2*>(&g_rp2[cell]);
            const int p2 = __ldg(&g_rp2[cell + 2]);
            const float4* Ea = reinterpret_cast<const float4*>(g_e2 + pq.x);
            const float4* Eb = reinterpret_cast<const float4*>(g_e2 + pq.y);
            const int ia = (pq.y - pq.x) >> 1;
            const int ib = (p2 - pq.y) >> 1;
            const int m  = min(ia, ib);
            float a00 = a[2*j], a01 = a[2*j+1], a10 = a[2*j+2], a11 = a[2*j+3];
            #pragma unroll 2
            for (int i = 0; i < m; i++) {
                float4 A = __ldg(Ea + i);
                float4 B = __ldg(Eb + i);
                float2 f;
                f = GX2(hl, A.y); a00 += A.x * f.x; a01 += A.x * f.y;
                f = GX2(hl, A.w); a00 += A.z * f.x; a01 += A.z * f.y;
                f = GX2(hl, B.y); a10 += B.x * f.x; a11 += B.x * f.y;
                f = GX2(hl, B.w); a10 += B.z * f.x; a11 += B.z * f.y;
            }
            for (int i = m; i < ia; i++) {
                float4 A = __ldg(Ea + i);
                float2 f;
                f = GX2(hl, A.y); a00 += A.x * f.x; a01 += A.x * f.y;
                f = GX2(hl, A.w); a00 += A.z * f.x; a01 += A.z * f.y;
            }
            for (int i = m; i < ib; i++) {
                float4 B = __ldg(Eb + i);
                float2 f;
                f = GX2(hl, B.y); a10 += B.x * f.x; a11 += B.x * f.y;
                f = GX2(hl, B.w); a10 += B.z * f.x; a11 += B.z * f.y;
            }
            a[2*j] = a00; a[2*j+1] = a01; a[2*j+2] = a10; a[2*j+3] = a11;
        }
    }

    __syncthreads();
    float* ost = reinterpret_cast<float*>(hsm);
    #pragma unroll
    for (int j = 0; j < 16; j++) {
        int row = w * 16 + j;
        ost[row * OSTR + 2 * lane]     = a[2 * j];
        ost[row * OSTR + 2 * lane + 1] = a[2 * j + 1];
    }
    __syncthreads();
    #pragma unroll
    for (int it = 0; it < 32; it++) {
        int idx = it * 1024 + tid;
        int b = idx >> 9;
        int r = idx & 511;
        out[(size_t)(b0 + b) * D_OUT + r] = ost[r * OSTR + b];
    }
}

// ---------------- launch: 5 kernels, k_l1 at index 3 (profiler slot) ---------
extern "C" void kernel_launch(void* const* d_in, const int* in_sizes, int n_in,
                              void* d_out, int out_size) {
    const float* x     = (const float*)d_in[0];
    const float* w1    = (const float*)d_in[1];
    const float* b1    = (const float*)d_in[2];
    const float* w2    = (const float*)d_in[3];
    const float* b2    = (const float*)d_in[4];
    const int*   rows1 = (const int*)d_in[5];
    const int*   cols1 = (const int*)d_in[6];
    const int*   rows2 = (const int*)d_in[7];
    const int*   cols2 = (const int*)d_in[8];
    float*       out   = (float*)d_out;

    k_prep<<<1, 1024>>>(rows1, cols1, rows2, cols2);
    k_scat1<<<NNZ1 / 256, 256>>>(w1, rows1, cols1);
    k_scat2<<<NNZ2 / 256, 256>>>(w2, rows2, cols2);

    const int SMEM1 = 4 * SUBT * 4;                           // 135168
    const int SMEM2 = D_OUT * OSTR * 4;                       // 137216
    cudaFuncSetAttribute(k_l1, cudaFuncAttributeMaxDynamicSharedMemorySize, SMEM1);
    cudaFuncSetAttribute(k_l2, cudaFuncAttributeMaxDynamicSharedMemorySize, SMEM2);
    k_l1<<<NBATCH / TB, 1024, SMEM1>>>(x, b1);
    k_l2<<<NBATCH / TB, 1024, SMEM2>>>(b2, out);
}

// round 10
// speedup vs baseline: 2.5035x; 1.1181x over previous
#include <cuda_runtime.h>
#include <cuda_fp16.h>

// Problem constants
#define D_IN    4096
#define D_HID   2048
#define D_OUT   512
#define NBATCH  8192
#define NNZ1    32768
#define NNZ2    8192
#define E1CAP   (NNZ1 + D_HID)       // +1 pad slot per row
#define E2CAP   (NNZ2 + D_OUT)
#define XPITCHB (NBATCH * 2)         // bytes per xt/g_h row (fp16)

// ---------------- scratch (__device__ globals) -------------------------------
__device__ __align__(16) float2 g_e1[E1CAP];   // {w as half2{w,w} bits, byteoff=c*16384}
__device__ __align__(16) float2 g_e2[E2CAP];   // {w fp32, byteoff=c*16384}
__device__ __align__(16) int g_rp1[D_HID + 4]; // even (16B-aligned) CSR starts
__device__ __align__(16) int g_rp2[D_OUT + 4];
__device__ int g_cur1[D_HID];
__device__ int g_cur2[D_OUT];
__device__ __align__(128) __half g_xt[(size_t)D_IN * NBATCH];  // [col][batch] 64 MB
__device__ __align__(128) __half g_h [(size_t)D_HID * NBATCH]; // [row][batch] 32 MB

// ---------------- helpers ----------------------------------------------------
__device__ __forceinline__ unsigned H2U(__half2 h) { return *reinterpret_cast<unsigned*>(&h); }
__device__ __forceinline__ __half2  U2H(unsigned u) { return *reinterpret_cast<__half2*>(&u); }
__device__ __forceinline__ float sigf(float v) {
    return __fdividef(1.0f, 1.0f + __expf(-v));
}

// ---------------- k_xt: x [batch][col] f32 -> xt [col][batch] fp16 -----------
__global__ __launch_bounds__(256) void k_xt(const float* __restrict__ x) {
    __shared__ unsigned tile[64 * 33];           // [col][batch-pair]
    const int C0  = blockIdx.x * 64;
    const int B0  = blockIdx.y * 64;
    const int tid = threadIdx.x;
    const int f4c = tid & 15;                    // float4-column 0..15 (64 cols)
    const int bp  = tid >> 4;                    // batch pair 0..15
    #pragma unroll
    for (int pass = 0; pass < 2; pass++) {
        int    bloc = bp + pass * 16;            // 0..31
        int    b    = B0 + 2 * bloc;
        float4 a = __ldg(reinterpret_cast<const float4*>(x + (size_t)b * D_IN + C0) + f4c);
        float4 c = __ldg(reinterpret_cast<const float4*>(x + (size_t)(b + 1) * D_IN + C0) + f4c);
        tile[(f4c * 4 + 0) * 33 + bloc] = H2U(__floats2half2_rn(a.x, c.x));
        tile[(f4c * 4 + 1) * 33 + bloc] = H2U(__floats2half2_rn(a.y, c.y));
        tile[(f4c * 4 + 2) * 33 + bloc] = H2U(__floats2half2_rn(a.z, c.z));
        tile[(f4c * 4 + 3) * 33 + bloc] = H2U(__floats2half2_rn(a.w, c.w));
    }
    __syncthreads();
    unsigned* xt32 = reinterpret_cast<unsigned*>(g_xt);
    const int wid  = tid >> 5;
    const int lane = tid & 31;
    #pragma unroll
    for (int pass = 0; pass < 8; pass++) {
        int c = pass * 8 + wid;
        xt32[(size_t)(C0 + c) * (NBATCH / 2) + (B0 >> 1) + lane] = tile[c * 33 + lane];
    }
}

// ---------------- k_prep: row hists + padded-even scans, ONE block -----------
__global__ __launch_bounds__(1024, 1)
void k_prep(const int* __restrict__ rows1, const int* __restrict__ rows2) {
    __shared__ int h1[D_HID];
    __shared__ int h2[D_OUT];
    __shared__ int ss[1024];
    const int t = threadIdx.x;

    for (int i = t; i < D_HID; i += 1024) h1[i] = 0;
    for (int i = t; i < D_OUT; i += 1024) h2[i] = 0;
    __syncthreads();
    for (int e = t; e < NNZ1; e += 1024) atomicAdd(&h1[__ldg(rows1 + e)], 1);
    for (int e = t; e < NNZ2; e += 1024) atomicAdd(&h2[__ldg(rows2 + e)], 1);
    __syncthreads();

    // scan h1 (2048 = 2/thread), pad each row to even length
    int r0 = h1[2 * t], r1 = h1[2 * t + 1];
    int p0 = (r0 + 1) & ~1, p1 = (r1 + 1) & ~1;
    ss[t] = p0 + p1;
    __syncthreads();
    for (int off = 1; off < 1024; off <<= 1) {
        int v = (t >= off) ? ss[t - off] : 0;
        __syncthreads();
        ss[t] += v;
        __syncthreads();
    }
    int ex = (t == 0) ? 0 : ss[t - 1];
    const float2 zed = make_float2(0.0f, 0.0f);
    g_rp1[2 * t] = ex; g_cur1[2 * t] = ex;
    if (r0 & 1) g_e1[ex + r0] = zed;             // zero the pad slot
    ex += p0;
    g_rp1[2 * t + 1] = ex; g_cur1[2 * t + 1] = ex;
    if (r1 & 1) g_e1[ex + r1] = zed;
    ex += p1;
    if (t == 1023) g_rp1[D_HID] = ex;
    __syncthreads();

    // scan h2 (512, first 512 threads active; syncs unconditional)
    int m0 = 0, q0 = 0;
    if (t < 512) { m0 = h2[t]; q0 = (m0 + 1) & ~1; }
    ss[t] = q0;
    __syncthreads();
    for (int off = 1; off < 512; off <<= 1) {
        int v = (t >= off && t < 512) ? ss[t - off] : 0;
        __syncthreads();
        if (t < 512) ss[t] += v;
        __syncthreads();
    }
    if (t < 512) {
        int ex2 = (t == 0) ? 0 : ss[t - 1];
        g_rp2[t] = ex2; g_cur2[t] = ex2;
        if (m0 & 1) g_e2[ex2 + m0] = zed;
        if (t == 511) g_rp2[D_OUT] = ex2 + q0;
    }
}

// ---------------- k_scat: both edge lists into padded CSR --------------------
__global__ void k_scat(const float* __restrict__ w1, const int* __restrict__ rows1,
                       const int* __restrict__ cols1,
                       const float* __restrict__ w2, const int* __restrict__ rows2,
                       const int* __restrict__ cols2) {
    int e = blockIdx.x * blockDim.x + threadIdx.x;
    if (e < NNZ1) {
        int p = atomicAdd(&g_cur1[rows1[e]], 1);
        __half2 wp = __float2half2_rn(w1[e]);
        g_e1[p] = make_float2(__uint_as_float(H2U(wp)),
                              __int_as_float(cols1[e] * XPITCHB));
    }
    if (e < NNZ2) {
        int p = atomicAdd(&g_cur2[rows2[e]], 1);
        g_e2[p] = make_float2(w2[e], __int_as_float(cols2[e] * XPITCHB));
    }
}

// ---------------- layer 1 edge stream: L2-direct gather, fp16 chain ----------
// One edge: LDG.64 pulls 4 batches (fp16) from the warp's 256B line; 2 HFMA2.
__device__ __forceinline__ void gacc1(__half2& a0, __half2& a1, const char* xb,
                                      float wbits, float obits) {
    float2 v = __ldg(reinterpret_cast<const float2*>(xb + __float_as_int(obits)));
    __half2 w = U2H(__float_as_uint(wbits));
    a0 = __hfma2(w, *reinterpret_cast<__half2*>(&v.x), a0);
    a1 = __hfma2(w, *reinterpret_cast<__half2*>(&v.y), a1);
}

__device__ __forceinline__ void pair_l1(__half2* A, __half2* B, const char* xb,
                                        int p0, int p1, int p2) {
    const float4* Ea = reinterpret_cast<const float4*>(g_e1 + p0);
    const float4* Eb = reinterpret_cast<const float4*>(g_e1 + p1);
    const int ia = (p1 - p0) >> 1;
    const int ib = (p2 - p1) >> 1;
    const int m  = min(ia, ib);
    #pragma unroll 2
    for (int i = 0; i < m; i++) {                // 4 independent gathers in flight
        float4 EA = __ldg(Ea + i);
        float4 EB = __ldg(Eb + i);
        gacc1(A[0], A[1], xb, EA.x, EA.y);
        gacc1(A[0], A[1], xb, EA.z, EA.w);
        gacc1(B[0], B[1], xb, EB.x, EB.y);
        gacc1(B[0], B[1], xb, EB.z, EB.w);
    }
    for (int i = m; i < ia; i++) {
        float4 EA = __ldg(Ea + i);
        gacc1(A[0], A[1], xb, EA.x, EA.y);
        gacc1(A[0], A[1], xb, EA.z, EA.w);
    }
    for (int i = m; i < ib; i++) {
        float4 EB = __ldg(Eb + i);
        gacc1(B[0], B[1], xb, EB.x, EB.y);
        gacc1(B[0], B[1], xb, EB.z, EB.w);
    }
}

// Block = 128 batches (lane = 4) x 256 rows (warp = 8 rows). No smem at all.
__global__ __launch_bounds__(1024, 1)
void k_l1(const float* __restrict__ b1) {
    const int w    = threadIdx.x >> 5;
    const int lane = threadIdx.x & 31;
    const int b0   = blockIdx.x * 128;
    const int r0   = blockIdx.y * 256 + w * 8;
    const char* xb = reinterpret_cast<const char*>(g_xt) + (size_t)(b0 + 4 * lane) * 2;

    __half2 acc[16];                             // 8 rows x 2 half2 (4 batches)
    #pragma unroll
    for (int j = 0; j < 8; j++) {
        __half2 bb = __float2half2_rn(__ldg(b1 + r0 + j));
        acc[2 * j] = bb;
        acc[2 * j + 1] = bb;
    }

    #pragma unroll 1
    for (int j = 0; j < 8; j += 2) {             // dual-row interleaved streams
        int pa = __ldg(&g_rp1[r0 + j]);
        int pb = __ldg(&g_rp1[r0 + j + 1]);
        int pc = __ldg(&g_rp1[r0 + j + 2]);
        pair_l1(acc + 2 * j, acc + 2 * j + 2, xb, pa, pb, pc);
    }

    #pragma unroll
    for (int j = 0; j < 8; j++) {                // sigmoid -> coalesced 8B stores
        float2 z0 = __half22float2(acc[2 * j]);
        float2 z1 = __half22float2(acc[2 * j + 1]);
        uint2 pk;
        pk.x = H2U(__floats2half2_rn(sigf(z0.x), sigf(z0.y)));
        pk.y = H2U(__floats2half2_rn(sigf(z1.x), sigf(z1.y)));
        *reinterpret_cast<uint2*>(&g_h[(size_t)(r0 + j) * NBATCH + b0 + 4 * lane]) = pk;
    }
}

// ---------------- layer 2: same shape, fp32 accumulation ---------------------
__device__ __forceinline__ void gacc2(float* a, const char* hb, float wv, float obits) {
    float2 v  = __ldg(reinterpret_cast<const float2*>(hb + __float_as_int(obits)));
    float2 f0 = __half22float2(*reinterpret_cast<__half2*>(&v.x));
    float2 f1 = __half22float2(*reinterpret_cast<__half2*>(&v.y));
    a[0] += wv * f0.x; a[1] += wv * f0.y;
    a[2] += wv * f1.x; a[3] += wv * f1.y;
}

__device__ __forceinline__ void pair_l2(float* A, float* B, const char* hb,
                                        int p0, int p1, int p2) {
    const float4* Ea = reinterpret_cast<const float4*>(g_e2 + p0);
    const float4* Eb = reinterpret_cast<const float4*>(g_e2 + p1);
    const int ia = (p1 - p0) >> 1;
    const int ib = (p2 - p1) >> 1;
    const int m  = min(ia, ib);
    #pragma unroll 2
    for (int i = 0; i < m; i++) {
        float4 EA = __ldg(Ea + i);
        float4 EB = __ldg(Eb + i);
        gacc2(A, hb, EA.x, EA.y);
        gacc2(A, hb, EA.z, EA.w);
        gacc2(B, hb, EB.x, EB.y);
        gacc2(B, hb, EB.z, EB.w);
    }
    for (int i = m; i < ia; i++) {
        float4 EA = __ldg(Ea + i);
        gacc2(A, hb, EA.x, EA.y);
        gacc2(A, hb, EA.z, EA.w);
    }
    for (int i = m; i < ib; i++) {
        float4 EB = __ldg(Eb + i);
        gacc2(B, hb, EB.x, EB.y);
        gacc2(B, hb, EB.z, EB.w);
    }
}

__global__ __launch_bounds__(1024, 1)
void k_l2(const float* __restrict__ b2, float* __restrict__ out) {
    const int w    = threadIdx.x >> 5;
    const int lane = threadIdx.x & 31;
    const int b0   = blockIdx.x * 128;
    const int r0   = blockIdx.y * 256 + w * 8;
    const char* hb = reinterpret_cast<const char*>(g_h) + (size_t)(b0 + 4 * lane) * 2;

    float a[32];                                 // [row 0..7][batch 0..3]
    #pragma unroll
    for (int j = 0; j < 8; j++) {
        float b = __ldg(b2 + r0 + j);
        a[4 * j] = b; a[4 * j + 1] = b; a[4 * j + 2] = b; a[4 * j + 3] = b;
    }

    #pragma unroll 1
    for (int j = 0; j < 8; j += 2) {
        int pa = __ldg(&g_rp2[r0 + j]);
        int pb = __ldg(&g_rp2[r0 + j + 1]);
        int pc = __ldg(&g_rp2[r0 + j + 2]);
        pair_l2(a + 4 * j, a + 4 * j + 4, hb, pa, pb, pc);
    }

    // per batch: 8 consecutive rows -> 2 STG.128 (r0 multiple of 8 -> aligned)
    #pragma unroll
    for (int k = 0; k < 4; k++) {
        float* op = out + (size_t)(b0 + 4 * lane + k) * D_OUT + r0;
        *reinterpret_cast<float4*>(op)     = make_float4(a[k], a[4 + k], a[8 + k], a[12 + k]);
        *reinterpret_cast<float4*>(op + 4) = make_float4(a[16 + k], a[20 + k], a[24 + k], a[28 + k]);
    }
}

// ---------------- launch: 5 kernels, k_l1 at index 3 (profiler slot) ---------
extern "C" void kernel_launch(void* const* d_in, const int* in_sizes, int n_in,
                              void* d_out, int out_size) {
    const float* x     = (const float*)d_in[0];
    const float* w1    = (const float*)d_in[1];
    const float* b1    = (const float*)d_in[2];
    const float* w2    = (const float*)d_in[3];
    const float* b2    = (const float*)d_in[4];
    const int*   rows1 = (const int*)d_in[5];
    const int*   cols1 = (const int*)d_in[6];
    const int*   rows2 = (const int*)d_in[7];
    const int*   cols2 = (const int*)d_in[8];
    float*       out   = (float*)d_out;

    k_xt  <<<dim3(D_IN / 64, NBATCH / 64), 256>>>(x);
    k_prep<<<1, 1024>>>(rows1, rows2);
    k_scat<<<NNZ1 / 256, 256>>>(w1, rows1, cols1, w2, rows2, cols2);
    k_l1  <<<dim3(NBATCH / 128, D_HID / 256), 1024>>>(b1);
    k_l2  <<<dim3(NBATCH / 128, D_OUT / 256), 1024>>>(b2, out);
}

// round 11
// speedup vs baseline: 2.9255x; 1.1686x over previous
#include <cuda_runtime.h>
#include <cuda_fp16.h>

// Problem constants
#define D_IN    4096
#define D_HID   2048
#define D_OUT   512
#define NBATCH  8192
#define NNZ1    32768
#define NNZ2    8192
#define E1CAP   (NNZ1 + D_HID)       // +1 pad slot per row
#define E2CAP   (NNZ2 + D_OUT)
#define XPITCHB (NBATCH * 2)         // bytes per xt/g_h row (fp16)

// ---------------- scratch (__device__ globals) -------------------------------
__device__ __align__(16) float2 g_e1[E1CAP];   // {w as half2{w,w} bits, byteoff=c*16384}
__device__ __align__(16) float2 g_e2[E2CAP];   // {w fp32, byteoff=c*16384}
__device__ __align__(16) int g_rp1[D_HID + 4]; // even (16B-aligned) CSR starts
__device__ __align__(16) int g_rp2[D_OUT + 4];
__device__ int g_cur1[D_HID];
__device__ int g_cur2[D_OUT];
__device__ __align__(128) __half g_xt[(size_t)D_IN * NBATCH];  // [col][batch] 64 MB
__device__ __align__(128) __half g_h [(size_t)D_HID * NBATCH]; // [row][batch] 32 MB

// ---------------- helpers ----------------------------------------------------
__device__ __forceinline__ unsigned H2U(__half2 h) { return *reinterpret_cast<unsigned*>(&h); }
__device__ __forceinline__ __half2  U2H(unsigned u) { return *reinterpret_cast<__half2*>(&u); }
__device__ __forceinline__ float sigf(float v) {
    return __fdividef(1.0f, 1.0f + __expf(-v));
}

// ---------------- k_xt: x [batch][col] f32 -> xt [col][batch] fp16 -----------
__global__ __launch_bounds__(256) void k_xt(const float* __restrict__ x) {
    __shared__ unsigned tile[64 * 33];           // [col][batch-pair]
    const int C0  = blockIdx.x * 64;
    const int B0  = blockIdx.y * 64;
    const int tid = threadIdx.x;
    const int f4c = tid & 15;                    // float4-column 0..15 (64 cols)
    const int bp  = tid >> 4;                    // batch pair 0..15
    #pragma unroll
    for (int pass = 0; pass < 2; pass++) {
        int    bloc = bp + pass * 16;            // 0..31
        int    b    = B0 + 2 * bloc;
        float4 a = __ldg(reinterpret_cast<const float4*>(x + (size_t)b * D_IN + C0) + f4c);
        float4 c = __ldg(reinterpret_cast<const float4*>(x + (size_t)(b + 1) * D_IN + C0) + f4c);
        tile[(f4c * 4 + 0) * 33 + bloc] = H2U(__floats2half2_rn(a.x, c.x));
        tile[(f4c * 4 + 1) * 33 + bloc] = H2U(__floats2half2_rn(a.y, c.y));
        tile[(f4c * 4 + 2) * 33 + bloc] = H2U(__floats2half2_rn(a.z, c.z));
        tile[(f4c * 4 + 3) * 33 + bloc] = H2U(__floats2half2_rn(a.w, c.w));
    }
    __syncthreads();
    unsigned* xt32 = reinterpret_cast<unsigned*>(g_xt);
    const int wid  = tid >> 5;
    const int lane = tid & 31;
    #pragma unroll
    for (int pass = 0; pass < 8; pass++) {
        int c = pass * 8 + wid;
        xt32[(size_t)(C0 + c) * (NBATCH / 2) + (B0 >> 1) + lane] = tile[c * 33 + lane];
    }
}

// ---------------- k_prep: row hists + padded-even scans, ONE block -----------
__global__ __launch_bounds__(1024, 1)
void k_prep(const int* __restrict__ rows1, const int* __restrict__ rows2) {
    __shared__ int h1[D_HID];
    __shared__ int h2[D_OUT];
    __shared__ int ss[1024];
    const int t = threadIdx.x;

    for (int i = t; i < D_HID; i += 1024) h1[i] = 0;
    for (int i = t; i < D_OUT; i += 1024) h2[i] = 0;
    __syncthreads();
    for (int e = t; e < NNZ1; e += 1024) atomicAdd(&h1[__ldg(rows1 + e)], 1);
    for (int e = t; e < NNZ2; e += 1024) atomicAdd(&h2[__ldg(rows2 + e)], 1);
    __syncthreads();

    int r0 = h1[2 * t], r1 = h1[2 * t + 1];
    int p0 = (r0 + 1) & ~1, p1 = (r1 + 1) & ~1;
    ss[t] = p0 + p1;
    __syncthreads();
    for (int off = 1; off < 1024; off <<= 1) {
        int v = (t >= off) ? ss[t - off] : 0;
        __syncthreads();
        ss[t] += v;
        __syncthreads();
    }
    int ex = (t == 0) ? 0 : ss[t - 1];
    const float2 zed = make_float2(0.0f, 0.0f);
    g_rp1[2 * t] = ex; g_cur1[2 * t] = ex;
    if (r0 & 1) g_e1[ex + r0] = zed;
    ex += p0;
    g_rp1[2 * t + 1] = ex; g_cur1[2 * t + 1] = ex;
    if (r1 & 1) g_e1[ex + r1] = zed;
    ex += p1;
    if (t == 1023) g_rp1[D_HID] = ex;
    __syncthreads();

    int m0 = 0, q0 = 0;
    if (t < 512) { m0 = h2[t]; q0 = (m0 + 1) & ~1; }
    ss[t] = q0;
    __syncthreads();
    for (int off = 1; off < 512; off <<= 1) {
        int v = (t >= off && t < 512) ? ss[t - off] : 0;
        __syncthreads();
        if (t < 512) ss[t] += v;
        __syncthreads();
    }
    if (t < 512) {
        int ex2 = (t == 0) ? 0 : ss[t - 1];
        g_rp2[t] = ex2; g_cur2[t] = ex2;
        if (m0 & 1) g_e2[ex2 + m0] = zed;
        if (t == 511) g_rp2[D_OUT] = ex2 + q0;
    }
}

// ---------------- k_scat: both edge lists into padded CSR --------------------
__global__ void k_scat(const float* __restrict__ w1, const int* __restrict__ rows1,
                       const int* __restrict__ cols1,
                       const float* __restrict__ w2, const int* __restrict__ rows2,
                       const int* __restrict__ cols2) {
    int e = blockIdx.x * blockDim.x + threadIdx.x;
    if (e < NNZ1) {
        int p = atomicAdd(&g_cur1[rows1[e]], 1);
        __half2 wp = __float2half2_rn(w1[e]);
        g_e1[p] = make_float2(__uint_as_float(H2U(wp)),
                              __int_as_float(cols1[e] * XPITCHB));
    }
    if (e < NNZ2) {
        int p = atomicAdd(&g_cur2[rows2[e]], 1);
        g_e2[p] = make_float2(w2[e], __int_as_float(cols2[e] * XPITCHB));
    }
}

// ---------------- layer 1 edge stream: lane = 8 batches, LDG.128 gather ------
__device__ __forceinline__ void gacc1(__half2* a, const char* xb,
                                      float wbits, float obits) {
    float4 v = __ldg(reinterpret_cast<const float4*>(xb + __float_as_int(obits)));
    __half2 w = U2H(__float_as_uint(wbits));
    a[0] = __hfma2(w, *reinterpret_cast<__half2*>(&v.x), a[0]);
    a[1] = __hfma2(w, *reinterpret_cast<__half2*>(&v.y), a[1]);
    a[2] = __hfma2(w, *reinterpret_cast<__half2*>(&v.z), a[2]);
    a[3] = __hfma2(w, *reinterpret_cast<__half2*>(&v.w), a[3]);
}

__device__ __forceinline__ void pair_l1(__half2* A, __half2* B, const char* xb,
                                        int p0, int p1, int p2) {
    const float4* Ea = reinterpret_cast<const float4*>(g_e1 + p0);
    const float4* Eb = reinterpret_cast<const float4*>(g_e1 + p1);
    const int ia = (p1 - p0) >> 1;
    const int ib = (p2 - p1) >> 1;
    const int m  = min(ia, ib);
    #pragma unroll 2
    for (int i = 0; i < m; i++) {                // 4 independent gathers in flight
        float4 EA = __ldg(Ea + i);
        float4 EB = __ldg(Eb + i);
        gacc1(A, xb, EA.x, EA.y);
        gacc1(A, xb, EA.z, EA.w);
        gacc1(B, xb, EB.x, EB.y);
        gacc1(B, xb, EB.z, EB.w);
    }
    for (int i = m; i < ia; i++) {
        float4 EA = __ldg(Ea + i);
        gacc1(A, xb, EA.x, EA.y);
        gacc1(A, xb, EA.z, EA.w);
    }
    for (int i = m; i < ib; i++) {
        float4 EB = __ldg(Eb + i);
        gacc1(B, xb, EB.x, EB.y);
        gacc1(B, xb, EB.z, EB.w);
    }
}

// Block = 512 thr (16 warps, 2 CTAs/SM). Warp = 8 rows x 256 batches (lane=8).
// Grid x = row-tile (fast) so concurrent CTAs share the same 2MB xt slice in L2.
__global__ __launch_bounds__(512, 2)
void k_l1(const float* __restrict__ b1) {
    const int w    = threadIdx.x >> 5;
    const int lane = threadIdx.x & 31;
    const int r0   = blockIdx.x * 128 + w * 8;
    const int b0   = blockIdx.y * 256;
    const char* xb = reinterpret_cast<const char*>(g_xt) + (size_t)(b0 + 8 * lane) * 2;

    __half2 acc[32];                             // 8 rows x 4 half2 (8 batches)
    #pragma unroll
    for (int j = 0; j < 8; j++) {
        __half2 bb = __float2half2_rn(__ldg(b1 + r0 + j));
        acc[4 * j] = bb; acc[4 * j + 1] = bb; acc[4 * j + 2] = bb; acc[4 * j + 3] = bb;
    }

    #pragma unroll 1
    for (int j = 0; j < 8; j += 2) {             // dual-row interleaved streams
        int pa = __ldg(&g_rp1[r0 + j]);
        int pb = __ldg(&g_rp1[r0 + j + 1]);
        int pc = __ldg(&g_rp1[r0 + j + 2]);
        pair_l1(acc + 4 * j, acc + 4 * j + 4, xb, pa, pb, pc);
    }

    #pragma unroll
    for (int j = 0; j < 8; j++) {                // sigmoid -> coalesced 16B stores
        float2 z0 = __half22float2(acc[4 * j]);
        float2 z1 = __half22float2(acc[4 * j + 1]);
        float2 z2 = __half22float2(acc[4 * j + 2]);
        float2 z3 = __half22float2(acc[4 * j + 3]);
        uint4 pk;
        pk.x = H2U(__floats2half2_rn(sigf(z0.x), sigf(z0.y)));
        pk.y = H2U(__floats2half2_rn(sigf(z1.x), sigf(z1.y)));
        pk.z = H2U(__floats2half2_rn(sigf(z2.x), sigf(z2.y)));
        pk.w = H2U(__floats2half2_rn(sigf(z3.x), sigf(z3.y)));
        *reinterpret_cast<uint4*>(&g_h[(size_t)(r0 + j) * NBATCH + b0 + 8 * lane]) = pk;
    }
}

// ---------------- layer 2: lane = 8 batches, fp32 accumulation ---------------
__device__ __forceinline__ void gacc2(float* a, const char* hb, float wv, float obits) {
    float4 v  = __ldg(reinterpret_cast<const float4*>(hb + __float_as_int(obits)));
    float2 f0 = __half22float2(*reinterpret_cast<__half2*>(&v.x));
    float2 f1 = __half22float2(*reinterpret_cast<__half2*>(&v.y));
    float2 f2 = __half22float2(*reinterpret_cast<__half2*>(&v.z));
    float2 f3 = __half22float2(*reinterpret_cast<__half2*>(&v.w));
    a[0] += wv * f0.x; a[1] += wv * f0.y;
    a[2] += wv * f1.x; a[3] += wv * f1.y;
    a[4] += wv * f2.x; a[5] += wv * f2.y;
    a[6] += wv * f3.x; a[7] += wv * f3.y;
}

__device__ __forceinline__ void pair_l2(float* A, float* B, const char* hb,
                                        int p0, int p1, int p2) {
    const float4* Ea = reinterpret_cast<const float4*>(g_e2 + p0);
    const float4* Eb = reinterpret_cast<const float4*>(g_e2 + p1);
    const int ia = (p1 - p0) >> 1;
    const int ib = (p2 - p1) >> 1;
    const int m  = min(ia, ib);
    #pragma unroll 2
    for (int i = 0; i < m; i++) {
        float4 EA = __ldg(Ea + i);
        float4 EB = __ldg(Eb + i);
        gacc2(A, hb, EA.x, EA.y);
        gacc2(A, hb, EA.z, EA.w);
        gacc2(B, hb, EB.x, EB.y);
        gacc2(B, hb, EB.z, EB.w);
    }
    for (int i = m; i < ia; i++) {
        float4 EA = __ldg(Ea + i);
        gacc2(A, hb, EA.x, EA.y);
        gacc2(A, hb, EA.z, EA.w);
    }
    for (int i = m; i < ib; i++) {
        float4 EB = __ldg(Eb + i);
        gacc2(B, hb, EB.x, EB.y);
        gacc2(B, hb, EB.z, EB.w);
    }
}

// Block = 512 thr. Warp = 4 rows x 256 batches (lane=8). 32 fp32 acc regs.
__global__ __launch_bounds__(512, 2)
void k_l2(const float* __restrict__ b2, float* __restrict__ out) {
    const int w    = threadIdx.x >> 5;
    const int lane = threadIdx.x & 31;
    const int r0   = blockIdx.x * 64 + w * 4;
    const int b0   = blockIdx.y * 256;
    const char* hb = reinterpret_cast<const char*>(g_h) + (size_t)(b0 + 8 * lane) * 2;

    float a[32];                                 // [row 0..3][batch 0..7]
    #pragma unroll
    for (int j = 0; j < 4; j++) {
        float b = __ldg(b2 + r0 + j);
        #pragma unroll
        for (int k = 0; k < 8; k++) a[8 * j + k] = b;
    }

    #pragma unroll 1
    for (int j = 0; j < 4; j += 2) {
        int pa = __ldg(&g_rp2[r0 + j]);
        int pb = __ldg(&g_rp2[r0 + j + 1]);
        int pc = __ldg(&g_rp2[r0 + j + 2]);
        pair_l2(a + 8 * j, a + 8 * j + 8, hb, pa, pb, pc);
    }

    // per batch: 4 consecutive rows -> STG.128 (r0 multiple of 4 -> aligned)
    #pragma unroll
    for (int k = 0; k < 8; k++) {
        float* op = out + (size_t)(b0 + 8 * lane + k) * D_OUT + r0;
        *reinterpret_cast<float4*>(op) =
            make_float4(a[k], a[8 + k], a[16 + k], a[24 + k]);
    }
}

// ---------------- launch: 5 kernels, k_l1 at index 3 (profiler slot) ---------
extern "C" void kernel_launch(void* const* d_in, const int* in_sizes, int n_in,
                              void* d_out, int out_size) {
    const float* x     = (const float*)d_in[0];
    const float* w1    = (const float*)d_in[1];
    const float* b1    = (const float*)d_in[2];
    const float* w2    = (const float*)d_in[3];
    const float* b2    = (const float*)d_in[4];
    const int*   rows1 = (const int*)d_in[5];
    const int*   cols1 = (const int*)d_in[6];
    const int*   rows2 = (const int*)d_in[7];
    const int*   cols2 = (const int*)d_in[8];
    float*       out   = (float*)d_out;

    k_xt  <<<dim3(D_IN / 64, NBATCH / 64), 256>>>(x);
    k_prep<<<1, 1024>>>(rows1, rows2);
    k_scat<<<NNZ1 / 256, 256>>>(w1, rows1, cols1, w2, rows2, cols2);
    k_l1  <<<dim3(D_HID / 128, NBATCH / 256), 512>>>(b1);
    k_l2  <<<dim3(D_OUT / 64, NBATCH / 256), 512>>>(b2, out);
}